// round 5
// baseline (speedup 1.0000x reference)
#include <cuda_runtime.h>
#include <math.h>
#include <stdint.h>

// Problem constants
#define TOK   4096         // B*N
#define CDIM  1024
#define HEADS 16
#define NBAT  4
#define NSEQ  1024
#define HD    64

// Scratch (device globals: allocation-free per harness rules)
__device__ __align__(256) float g_h[TOK * CDIM];                              // 16 MB
__device__ __align__(256) float g_qkv[TOK * 3 * CDIM];                        // 48 MB
__device__ __align__(256) float g_s[(size_t)NBAT * HEADS * NSEQ * NSEQ];      // 256 MB
__device__ __align__(256) float g_attn[TOK * CDIM];                           // 16 MB
__device__ __align__(256) float g_mlp[TOK * 4 * CDIM];                        // 64 MB (also rounded-c)
__device__ __align__(256) float g_wt[4 * 1024 * 1024];                        // 16 MB (transposed weights)
__device__ __align__(256) float g_vt[(size_t)NBAT * HEADS * HD * NSEQ];       // 16 MB (transposed V)

// ---------------------------------------------------------------------------
// Helpers
// ---------------------------------------------------------------------------
__device__ __forceinline__ uint32_t smem_u32(const void* p) {
    uint32_t a;
    asm("{ .reg .u64 t; cvta.to.shared.u64 t, %1; cvt.u32.u64 %0, t; }" : "=r"(a) : "l"(p));
    return a;
}
__device__ __forceinline__ float rnd_tf32(float x) {
    uint32_t u;
    asm("cvt.rna.tf32.f32 %0, %1;" : "=r"(u) : "f"(x));
    return __uint_as_float(u);
}
#define CP_ASYNC16(dst, src) \
    asm volatile("cp.async.cg.shared.global [%0], [%1], 16;" :: "r"(dst), "l"(src) : "memory")
#define CP_COMMIT()  asm volatile("cp.async.commit_group;" ::: "memory")

__device__ __forceinline__ void mma8(float* d, const uint32_t* a, const uint32_t* b) {
    asm volatile("mma.sync.aligned.m16n8k8.row.col.f32.tf32.tf32.f32 "
                 "{%0,%1,%2,%3}, {%4,%5,%6,%7}, {%8,%9}, {%0,%1,%2,%3};"
                 : "+f"(d[0]), "+f"(d[1]), "+f"(d[2]), "+f"(d[3])
                 : "r"(a[0]), "r"(a[1]), "r"(a[2]), "r"(a[3]), "r"(b[0]), "r"(b[1]));
}

// ---------------------------------------------------------------------------
// LayerNorm (no affine, eps=1e-6), rounds output to tf32 (it feeds MMA only)
// ---------------------------------------------------------------------------
__global__ void ln_kernel(const float* __restrict__ in, float* __restrict__ out) {
    __shared__ float sred[256];
    int row = blockIdx.x;
    const float4* p = (const float4*)(in + (size_t)row * CDIM);
    float4 v = p[threadIdx.x];
    float s = v.x + v.y + v.z + v.w;
    sred[threadIdx.x] = s; __syncthreads();
    for (int o = 128; o > 0; o >>= 1) {
        if (threadIdx.x < o) sred[threadIdx.x] += sred[threadIdx.x + o];
        __syncthreads();
    }
    float mean = sred[0] * (1.f / CDIM);
    __syncthreads();
    float dx = v.x-mean, dy = v.y-mean, dz = v.z-mean, dw = v.w-mean;
    sred[threadIdx.x] = dx*dx + dy*dy + dz*dz + dw*dw; __syncthreads();
    for (int o = 128; o > 0; o >>= 1) {
        if (threadIdx.x < o) sred[threadIdx.x] += sred[threadIdx.x + o];
        __syncthreads();
    }
    float inv = rsqrtf(sred[0] * (1.f / CDIM) + 1e-6f);
    float4 r = make_float4(rnd_tf32(dx*inv), rnd_tf32(dy*inv),
                           rnd_tf32(dz*inv), rnd_tf32(dw*inv));
    ((float4*)(out + (size_t)row * CDIM))[threadIdx.x] = r;
}

// ---------------------------------------------------------------------------
// Masked softmax; S and mask pointers are pre-offset to the batch chunk.
// grid.x = HEADS*NSEQ rows of length NSEQ. Output rounded to tf32.
// ---------------------------------------------------------------------------
__global__ void softmax_kernel(float* __restrict__ S, const int* __restrict__ mask) {
    __shared__ float sred[256];
    size_t row = blockIdx.x;
    float4* p = (float4*)(S + row * NSEQ);
    const int4* mrow = (const int4*)mask;
    const float scale = 0.125f;
    float4 v = p[threadIdx.x];
    int4 m = mrow[threadIdx.x];
    v.x = v.x * scale + ((m.x == 1) ? 0.f : -10000.f);
    v.y = v.y * scale + ((m.y == 1) ? 0.f : -10000.f);
    v.z = v.z * scale + ((m.z == 1) ? 0.f : -10000.f);
    v.w = v.w * scale + ((m.w == 1) ? 0.f : -10000.f);
    float mx = fmaxf(fmaxf(v.x, v.y), fmaxf(v.z, v.w));
    sred[threadIdx.x] = mx; __syncthreads();
    for (int o = 128; o > 0; o >>= 1) {
        if (threadIdx.x < o) sred[threadIdx.x] = fmaxf(sred[threadIdx.x], sred[threadIdx.x + o]);
        __syncthreads();
    }
    mx = sred[0]; __syncthreads();
    v.x = __expf(v.x - mx); v.y = __expf(v.y - mx);
    v.z = __expf(v.z - mx); v.w = __expf(v.w - mx);
    sred[threadIdx.x] = v.x + v.y + v.z + v.w; __syncthreads();
    for (int o = 128; o > 0; o >>= 1) {
        if (threadIdx.x < o) sred[threadIdx.x] += sred[threadIdx.x + o];
        __syncthreads();
    }
    float inv = 1.f / sred[0];
    v.x = rnd_tf32(v.x * inv); v.y = rnd_tf32(v.y * inv);
    v.z = rnd_tf32(v.z * inv); v.w = rnd_tf32(v.w * inv);
    p[threadIdx.x] = v;
}

// ---------------------------------------------------------------------------
// Elementwise round-to-tf32 copy (for raw c input feeding K/V GEMMs)
// ---------------------------------------------------------------------------
__global__ void round_copy(const float* __restrict__ in, float* __restrict__ out) {
    size_t i = (size_t)blockIdx.x * 256 + threadIdx.x;
    float4 v = ((const float4*)in)[i];
    v.x = rnd_tf32(v.x); v.y = rnd_tf32(v.y);
    v.z = rnd_tf32(v.z); v.w = rnd_tf32(v.w);
    ((float4*)out)[i] = v;
}

// ---------------------------------------------------------------------------
// Batched 32x32 tiled transpose, output rounded to tf32 (feeds MMA B operand)
// ---------------------------------------------------------------------------
__global__ void transpose_kernel(const float* __restrict__ in, float* __restrict__ out,
                                 int ldin, int ldout, int Hdiv,
                                 long long sInB, long long sInH,
                                 long long sOutB, long long sOutH) {
    __shared__ float t[32][33];
    int z = blockIdx.z;
    int zb = z / Hdiv, zh = z % Hdiv;
    in  += zb * sInB + zh * sInH;
    out += zb * sOutB + zh * sOutH;
    int c0 = blockIdx.x * 32, r0 = blockIdx.y * 32;
    int x = threadIdx.x, y = threadIdx.y;
#pragma unroll
    for (int i = 0; i < 32; i += 8)
        t[y + i][x] = in[(size_t)(r0 + y + i) * ldin + c0 + x];
    __syncthreads();
#pragma unroll
    for (int i = 0; i < 32; i += 8)
        out[(size_t)(c0 + y + i) * ldout + r0 + x] = rnd_tf32(t[x][y + i]);
}

// ---------------------------------------------------------------------------
// tf32 mma.sync GEMM. C[M,N] = A[M,K] @ B[N,K]^T (+bias)(+GELU)(+res)(+round)
// Tiles: BM x BN, BK=32. Warp grid (BM/64) x 4, warp tile 64 x (BN/4).
// A,B K-major; 3-stage cp.async pipeline. Batched via blockIdx.z.
// mode: bit0 = GELU, bit1 = round output to tf32.
// ---------------------------------------------------------------------------
template <int BM, int BN>
__global__ void __launch_bounds__((BM/64)*128, (BM == 128) ? 2 : 1)
mm_mma(const float* __restrict__ A, const float* __restrict__ B,
       const float* __restrict__ bias, const float* __restrict__ res,
       float* __restrict__ C, int K, int lda, int ldb, int ldc, int mode,
       int Hdiv, long long sAb, long long sAh, long long sBb, long long sBh,
       long long sCb, long long sCh) {
    constexpr int BK = 32, AST = BK + 4;               // padded stride (floats)
    constexpr int WARPSN = 4;
    constexpr int THREADS = (BM/64) * 128;
    constexpr int ASTAGE = BM * AST * 4;               // bytes
    constexpr int BSTAGE = BN * AST * 4;
    constexpr int WN = BN / 4;                         // 32 or 16
    constexpr int NT = WN / 8;                         // 4 or 2
    constexpr int MT = 4;                              // 64/16

    extern __shared__ char smem[];
    uint32_t sb = smem_u32(smem);
    uint32_t aoff[3] = { 0u, (uint32_t)ASTAGE, 2u * ASTAGE };
    uint32_t boff[3] = { 3u * ASTAGE, 3u * ASTAGE + BSTAGE, 3u * ASTAGE + 2u * BSTAGE };

    int tid = threadIdx.x;
    int wid = tid >> 5, lane = tid & 31;
    int warpM = wid / WARPSN, warpN = wid % WARPSN;
    int lr = lane >> 2, lc = lane & 3;

    int z = blockIdx.z;
    int bb = z / Hdiv, hh = z % Hdiv;
    A += bb * sAb + hh * sAh;
    B += bb * sBb + hh * sBh;
    long long cOff = bb * sCb + hh * sCh;
    C += cOff;
    if (res) res += cOff;

    int rowBase = blockIdx.y * BM;
    int colBase = blockIdx.x * BN;

    float acc[MT][NT][4];
#pragma unroll
    for (int i = 0; i < MT; i++)
#pragma unroll
        for (int j = 0; j < NT; j++)
#pragma unroll
            for (int q = 0; q < 4; q++) acc[i][j][q] = 0.f;

    auto load_stage = [&](int buf, int k0) {
#pragma unroll
        for (int i = 0; i < (BM * 8) / THREADS; i++) {
            int idx = tid + i * THREADS;
            int row = idx >> 3, c = idx & 7;
            uint32_t dst = sb + aoff[buf] + (uint32_t)(row * (AST * 4) + c * 16);
            const float* src = A + (size_t)(rowBase + row) * lda + k0 + c * 4;
            CP_ASYNC16(dst, src);
        }
#pragma unroll
        for (int i = 0; i < (BN * 8) / THREADS; i++) {
            int idx = tid + i * THREADS;
            int row = idx >> 3, c = idx & 7;
            uint32_t dst = sb + boff[buf] + (uint32_t)(row * (AST * 4) + c * 16);
            const float* src = B + (size_t)(colBase + row) * ldb + k0 + c * 4;
            CP_ASYNC16(dst, src);
        }
        CP_COMMIT();
    };

    int nsteps = K / BK;
    load_stage(0, 0);
    load_stage(1, BK);
    load_stage(2, 2 * BK);

    for (int s = 0; s < nsteps; s++) {
        int buf = s % 3;
        int rem = nsteps - 1 - s;
        if (rem >= 2)      asm volatile("cp.async.wait_group 2;" ::: "memory");
        else if (rem == 1) asm volatile("cp.async.wait_group 1;" ::: "memory");
        else               asm volatile("cp.async.wait_group 0;" ::: "memory");
        __syncthreads();

        const uint32_t* As = (const uint32_t*)(smem + aoff[buf]);
        const uint32_t* Bs = (const uint32_t*)(smem + boff[buf]);
#pragma unroll
        for (int kk = 0; kk < BK; kk += 8) {
            uint32_t af[MT][4], bf[NT][2];
#pragma unroll
            for (int i = 0; i < MT; i++) {
                int m0 = warpM * 64 + i * 16 + lr;
                int k = kk + lc;
                af[i][0] = As[m0 * AST + k];
                af[i][1] = As[(m0 + 8) * AST + k];
                af[i][2] = As[m0 * AST + k + 4];
                af[i][3] = As[(m0 + 8) * AST + k + 4];
            }
#pragma unroll
            for (int j = 0; j < NT; j++) {
                int n0 = warpN * WN + j * 8 + lr;
                int k = kk + lc;
                bf[j][0] = Bs[n0 * AST + k];
                bf[j][1] = Bs[n0 * AST + k + 4];
            }
#pragma unroll
            for (int i = 0; i < MT; i++)
#pragma unroll
                for (int j = 0; j < NT; j++)
                    mma8(acc[i][j], af[i], bf[j]);
        }
        __syncthreads();
        if (s + 3 < nsteps) load_stage(buf, (s + 3) * BK);
    }

    // Epilogue
    bool gelu = mode & 1, rnd = mode & 2;
#pragma unroll
    for (int i = 0; i < MT; i++) {
#pragma unroll
        for (int j = 0; j < NT; j++) {
#pragma unroll
            for (int h = 0; h < 2; h++) {
                int r = rowBase + warpM * 64 + i * 16 + lr + h * 8;
                int cb = colBase + warpN * WN + j * 8 + lc * 2;
                float v0 = acc[i][j][h * 2 + 0];
                float v1 = acc[i][j][h * 2 + 1];
                if (bias) { v0 += bias[cb]; v1 += bias[cb + 1]; }
                if (gelu) {
                    v0 = 0.5f * v0 * (1.f + erff(v0 * 0.70710678118654752f));
                    v1 = 0.5f * v1 * (1.f + erff(v1 * 0.70710678118654752f));
                }
                if (rnd) { v0 = rnd_tf32(v0); v1 = rnd_tf32(v1); }
                size_t o = (size_t)r * ldc + cb;
                if (res) {
                    float2 rv = *(const float2*)(res + o);
                    v0 += rv.x; v1 += rv.y;
                }
                float2 out = make_float2(v0, v1);
                *(float2*)(C + o) = out;
            }
        }
    }
}

// ---------------------------------------------------------------------------
// Host-side launch orchestration
// ---------------------------------------------------------------------------
extern "C" void kernel_launch(void* const* d_in, const int* in_sizes, int n_in,
                              void* d_out, int out_size) {
    const float* x_in     = (const float*)d_in[0];
    const float* c_in     = (const float*)d_in[1];
    const int*   mask     = (const int*)d_in[2];
    const float* sa_qkv_w = (const float*)d_in[3];
    const float* sa_qkv_b = (const float*)d_in[4];
    const float* sa_proj_w= (const float*)d_in[5];
    const float* sa_proj_b= (const float*)d_in[6];
    const float* ca_q_w   = (const float*)d_in[7];
    const float* ca_q_b   = (const float*)d_in[8];
    const float* ca_k_w   = (const float*)d_in[9];
    const float* ca_k_b   = (const float*)d_in[10];
    const float* ca_v_w   = (const float*)d_in[11];
    const float* ca_v_b   = (const float*)d_in[12];
    const float* ca_proj_w= (const float*)d_in[13];
    const float* ca_proj_b= (const float*)d_in[14];
    const float* fc1_w    = (const float*)d_in[15];
    const float* fc1_b    = (const float*)d_in[16];
    const float* fc2_w    = (const float*)d_in[17];
    const float* fc2_b    = (const float*)d_in[18];

    float* xb = (float*)d_out;

    float *gh, *gqkv, *gs, *gattn, *gmlp, *gwt, *gvt;
    cudaGetSymbolAddress((void**)&gh,    g_h);
    cudaGetSymbolAddress((void**)&gqkv,  g_qkv);
    cudaGetSymbolAddress((void**)&gs,    g_s);
    cudaGetSymbolAddress((void**)&gattn, g_attn);
    cudaGetSymbolAddress((void**)&gmlp,  g_mlp);
    cudaGetSymbolAddress((void**)&gwt,   g_wt);
    cudaGetSymbolAddress((void**)&gvt,   g_vt);

    const int AST4 = (32 + 4) * 4;
    const int SM256_128 = 3 * (256 * AST4 + 128 * AST4);  // 165888
    const int SM128_128 = 3 * (128 * AST4 + 128 * AST4);  // 110592
    const int SM128_64  = 3 * (128 * AST4 +  64 * AST4);  // 82944
    cudaFuncSetAttribute(mm_mma<256,128>, cudaFuncAttributeMaxDynamicSharedMemorySize, SM256_128);
    cudaFuncSetAttribute(mm_mma<128,128>, cudaFuncAttributeMaxDynamicSharedMemorySize, SM128_128);
    cudaFuncSetAttribute(mm_mma<128,64>,  cudaFuncAttributeMaxDynamicSharedMemorySize, SM128_64);

    const long long Z = 0;
    dim3 tblock(32, 8);

    cudaMemcpyAsync(xb, x_in, (size_t)TOK * CDIM * sizeof(float),
                    cudaMemcpyDeviceToDevice, 0);

    // ===================== self-attention =====================
    ln_kernel<<<TOK, 256>>>(xb, gh);

    transpose_kernel<<<dim3(3072/32, 1024/32, 1), tblock>>>(sa_qkv_w, gwt, 3072, 1024, 1, Z,Z,Z,Z);
    mm_mma<256,128><<<dim3(3072/128, TOK/256, 1), 512, SM256_128>>>(
        gh, gwt, sa_qkv_b, nullptr, gqkv, 1024, 1024, 1024, 3072, 2,
        1, Z,Z,Z,Z,Z,Z);

    // Vt: [b,h,d,seq] (for all batches; consumed per-batch below)
    transpose_kernel<<<dim3(HD/32, NSEQ/32, NBAT*HEADS), tblock>>>(
        gqkv + 2*CDIM, gvt, 3072, NSEQ, HEADS,
        (long long)NSEQ*3*CDIM, HD, (long long)HEADS*HD*NSEQ, (long long)HD*NSEQ);

    // Attention per batch: S chunk (64 MB) stays L2-resident across QK/softmax/PV
    for (int b = 0; b < NBAT; b++) {
        float* Sb = gs + (size_t)b * HEADS * NSEQ * NSEQ;
        const float* Qb = gqkv + (size_t)b * NSEQ * 3 * CDIM;
        const float* Kb = Qb + CDIM;
        mm_mma<128,128><<<dim3(NSEQ/128, NSEQ/128, HEADS), 256, SM128_128>>>(
            Qb, Kb, nullptr, nullptr, Sb, HD, 3072, 3072, NSEQ, 0,
            HEADS, Z, HD, Z, HD, Z, (long long)NSEQ*NSEQ);
        softmax_kernel<<<HEADS*NSEQ, 256>>>(Sb, mask + b * NSEQ);
        mm_mma<128,64><<<dim3(1, NSEQ/128, HEADS), 256, SM128_64>>>(
            Sb, gvt + (size_t)b * HEADS * HD * NSEQ, nullptr, nullptr,
            gattn + (size_t)b * NSEQ * CDIM, NSEQ, NSEQ, NSEQ, CDIM, 2,
            HEADS, Z, (long long)NSEQ*NSEQ, Z, (long long)HD*NSEQ, Z, HD);
    }

    // x += attn @ sa_proj_w + b
    transpose_kernel<<<dim3(1024/32, 1024/32, 1), tblock>>>(sa_proj_w, gwt, 1024, 1024, 1, Z,Z,Z,Z);
    mm_mma<256,128><<<dim3(CDIM/128, TOK/256, 1), 512, SM256_128>>>(
        gattn, gwt, sa_proj_b, xb, xb, 1024, 1024, 1024, 1024, 0,
        1, Z,Z,Z,Z,Z,Z);

    // ===================== cross-attention =====================
    ln_kernel<<<TOK, 256>>>(xb, gh);

    float* gq = gqkv;
    float* gk = gqkv + (size_t)TOK * CDIM;
    float* gv = gqkv + (size_t)2 * TOK * CDIM;
    float* gcr = gmlp;   // gmlp is free until the MLP phase: rounded copy of c

    round_copy<<<TOK * CDIM / 4 / 256, 256>>>(c_in, gcr);

    transpose_kernel<<<dim3(1024/32, 1024/32, 1), tblock>>>(ca_q_w, gwt, 1024, 1024, 1, Z,Z,Z,Z);
    mm_mma<256,128><<<dim3(CDIM/128, TOK/256, 1), 512, SM256_128>>>(
        gh, gwt, ca_q_b, nullptr, gq, 1024, 1024, 1024, 1024, 2, 1, Z,Z,Z,Z,Z,Z);
    transpose_kernel<<<dim3(1024/32, 1024/32, 1), tblock>>>(ca_k_w, gwt, 1024, 1024, 1, Z,Z,Z,Z);
    mm_mma<256,128><<<dim3(CDIM/128, TOK/256, 1), 512, SM256_128>>>(
        gcr, gwt, ca_k_b, nullptr, gk, 1024, 1024, 1024, 1024, 2, 1, Z,Z,Z,Z,Z,Z);
    transpose_kernel<<<dim3(1024/32, 1024/32, 1), tblock>>>(ca_v_w, gwt, 1024, 1024, 1, Z,Z,Z,Z);
    mm_mma<256,128><<<dim3(CDIM/128, TOK/256, 1), 512, SM256_128>>>(
        gcr, gwt, ca_v_b, nullptr, gv, 1024, 1024, 1024, 1024, 2, 1, Z,Z,Z,Z,Z,Z);

    transpose_kernel<<<dim3(HD/32, NSEQ/32, NBAT*HEADS), tblock>>>(
        gv, gvt, 1024, NSEQ, HEADS,
        (long long)NSEQ*CDIM, HD, (long long)HEADS*HD*NSEQ, (long long)HD*NSEQ);

    for (int b = 0; b < NBAT; b++) {
        float* Sb = gs + (size_t)b * HEADS * NSEQ * NSEQ;
        const float* Qb = gq + (size_t)b * NSEQ * CDIM;
        const float* Kb = gk + (size_t)b * NSEQ * CDIM;
        mm_mma<128,128><<<dim3(NSEQ/128, NSEQ/128, HEADS), 256, SM128_128>>>(
            Qb, Kb, nullptr, nullptr, Sb, HD, 1024, 1024, NSEQ, 0,
            HEADS, Z, HD, Z, HD, Z, (long long)NSEQ*NSEQ);
        softmax_kernel<<<HEADS*NSEQ, 256>>>(Sb, mask + b * NSEQ);
        mm_mma<128,64><<<dim3(1, NSEQ/128, HEADS), 256, SM128_64>>>(
            Sb, gvt + (size_t)b * HEADS * HD * NSEQ, nullptr, nullptr,
            gattn + (size_t)b * NSEQ * CDIM, NSEQ, NSEQ, NSEQ, CDIM, 2,
            HEADS, Z, (long long)NSEQ*NSEQ, Z, (long long)HD*NSEQ, Z, HD);
    }

    transpose_kernel<<<dim3(1024/32, 1024/32, 1), tblock>>>(ca_proj_w, gwt, 1024, 1024, 1, Z,Z,Z,Z);
    mm_mma<256,128><<<dim3(CDIM/128, TOK/256, 1), 512, SM256_128>>>(
        gattn, gwt, ca_proj_b, xb, xb, 1024, 1024, 1024, 1024, 0, 1, Z,Z,Z,Z,Z,Z);

    // ===================== MLP =====================
    ln_kernel<<<TOK, 256>>>(xb, gh);

    transpose_kernel<<<dim3(4096/32, 1024/32, 1), tblock>>>(fc1_w, gwt, 4096, 1024, 1, Z,Z,Z,Z);
    mm_mma<256,128><<<dim3(4096/128, TOK/256, 1), 512, SM256_128>>>(
        gh, gwt, fc1_b, nullptr, gmlp, 1024, 1024, 1024, 4096, 3, 1, Z,Z,Z,Z,Z,Z);

    transpose_kernel<<<dim3(1024/32, 4096/32, 1), tblock>>>(fc2_w, gwt, 1024, 4096, 1, Z,Z,Z,Z);
    mm_mma<256,128><<<dim3(CDIM/128, TOK/256, 1), 512, SM256_128>>>(
        gmlp, gwt, fc2_b, xb, xb, 4096, 4096, 4096, 1024, 0, 1, Z,Z,Z,Z,Z,Z);
}

// round 6
// speedup vs baseline: 1.2855x; 1.2855x over previous
#include <cuda_runtime.h>
#include <math.h>
#include <stdint.h>

// Problem constants
#define TOK   4096         // B*N
#define CDIM  1024
#define HEADS 16
#define NBAT  4
#define NSEQ  1024
#define HD    64

// Scratch (device globals: allocation-free per harness rules)
__device__ __align__(256) float g_h[TOK * CDIM];                              // 16 MB
__device__ __align__(256) float g_qkv[TOK * 3 * CDIM];                        // 48 MB
__device__ __align__(256) float g_attn[TOK * CDIM];                           // 16 MB
__device__ __align__(256) float g_mlp[TOK * 4 * CDIM];                        // 64 MB (also rounded-c)
__device__ __align__(256) float g_wt[4 * 1024 * 1024];                        // 16 MB (transposed weights)

// ---------------------------------------------------------------------------
// Helpers
// ---------------------------------------------------------------------------
__device__ __forceinline__ uint32_t smem_u32(const void* p) {
    uint32_t a;
    asm("{ .reg .u64 t; cvta.to.shared.u64 t, %1; cvt.u32.u64 %0, t; }" : "=r"(a) : "l"(p));
    return a;
}
__device__ __forceinline__ float rnd_tf32(float x) {
    uint32_t u;
    asm("cvt.rna.tf32.f32 %0, %1;" : "=r"(u) : "f"(x));
    return __uint_as_float(u);
}
#define CP_ASYNC16(dst, src) \
    asm volatile("cp.async.cg.shared.global [%0], [%1], 16;" :: "r"(dst), "l"(src) : "memory")
#define CP_COMMIT()  asm volatile("cp.async.commit_group;" ::: "memory")

__device__ __forceinline__ void mma8(float* d, const uint32_t* a, const uint32_t* b) {
    asm volatile("mma.sync.aligned.m16n8k8.row.col.f32.tf32.tf32.f32 "
                 "{%0,%1,%2,%3}, {%4,%5,%6,%7}, {%8,%9}, {%0,%1,%2,%3};"
                 : "+f"(d[0]), "+f"(d[1]), "+f"(d[2]), "+f"(d[3])
                 : "r"(a[0]), "r"(a[1]), "r"(a[2]), "r"(a[3]), "r"(b[0]), "r"(b[1]));
}

// ---------------------------------------------------------------------------
// LayerNorm (no affine, eps=1e-6), rounds output to tf32 (it feeds MMA only)
// ---------------------------------------------------------------------------
__global__ void ln_kernel(const float* __restrict__ in, float* __restrict__ out) {
    __shared__ float sred[256];
    int row = blockIdx.x;
    const float4* p = (const float4*)(in + (size_t)row * CDIM);
    float4 v = p[threadIdx.x];
    float s = v.x + v.y + v.z + v.w;
    sred[threadIdx.x] = s; __syncthreads();
    for (int o = 128; o > 0; o >>= 1) {
        if (threadIdx.x < o) sred[threadIdx.x] += sred[threadIdx.x + o];
        __syncthreads();
    }
    float mean = sred[0] * (1.f / CDIM);
    __syncthreads();
    float dx = v.x-mean, dy = v.y-mean, dz = v.z-mean, dw = v.w-mean;
    sred[threadIdx.x] = dx*dx + dy*dy + dz*dz + dw*dw; __syncthreads();
    for (int o = 128; o > 0; o >>= 1) {
        if (threadIdx.x < o) sred[threadIdx.x] += sred[threadIdx.x + o];
        __syncthreads();
    }
    float inv = rsqrtf(sred[0] * (1.f / CDIM) + 1e-6f);
    float4 r = make_float4(rnd_tf32(dx*inv), rnd_tf32(dy*inv),
                           rnd_tf32(dz*inv), rnd_tf32(dw*inv));
    ((float4*)(out + (size_t)row * CDIM))[threadIdx.x] = r;
}

// ---------------------------------------------------------------------------
// Elementwise round-to-tf32 copy (for raw c input feeding K/V GEMMs)
// ---------------------------------------------------------------------------
__global__ void round_copy(const float* __restrict__ in, float* __restrict__ out) {
    size_t i = (size_t)blockIdx.x * 256 + threadIdx.x;
    float4 v = ((const float4*)in)[i];
    v.x = rnd_tf32(v.x); v.y = rnd_tf32(v.y);
    v.z = rnd_tf32(v.z); v.w = rnd_tf32(v.w);
    ((float4*)out)[i] = v;
}

// ---------------------------------------------------------------------------
// 32x32 tiled transpose for weights, output rounded to tf32
// ---------------------------------------------------------------------------
__global__ void transpose_kernel(const float* __restrict__ in, float* __restrict__ out,
                                 int ldin, int ldout) {
    __shared__ float t[32][33];
    int c0 = blockIdx.x * 32, r0 = blockIdx.y * 32;
    int x = threadIdx.x, y = threadIdx.y;
#pragma unroll
    for (int i = 0; i < 32; i += 8)
        t[y + i][x] = in[(size_t)(r0 + y + i) * ldin + c0 + x];
    __syncthreads();
#pragma unroll
    for (int i = 0; i < 32; i += 8)
        out[(size_t)(c0 + y + i) * ldout + r0 + x] = rnd_tf32(t[x][y + i]);
}

// ---------------------------------------------------------------------------
// Fused flash-attention (tf32 mma.sync), non-causal, additive key mask.
//   Per CTA: 128 query rows of one (batch, head). 256 threads, 8 warps,
//   warp w owns Q rows [16w, 16w+16). K/V streamed in 128-key chunks,
//   double-buffered cp.async. S in regs, online softmax, O accumulated in
//   regs, normalized + rounded to tf32 at the end.
//   Q/K/V are K-major rows with common ld and (batch, head) strides.
// ---------------------------------------------------------------------------
__global__ void __launch_bounds__(256, 1)
flash_kernel(const float* __restrict__ Qp, const float* __restrict__ Kp,
             const float* __restrict__ Vp, const int* __restrict__ mask,
             float* __restrict__ Op, int ld, int ldo,
             long long sBat, long long sHead, long long sOb, long long sOh) {
    constexpr int ST  = 68;          // floats per smem row (64 + 4 pad)
    constexpr int RB  = ST * 4;      // 272 bytes
    constexpr int TSZ = 128 * RB;    // 34816 bytes per tile
    const int KS = TSZ;              // K bufs at TSZ, 2*TSZ
    const int VS = TSZ * 3;          // V bufs at 3*TSZ, 4*TSZ
    const int MK = TSZ * 5;          // mask bufs 512B each

    extern __shared__ char smem[];
    uint32_t sb = smem_u32(smem);

    int tid = threadIdx.x, w = tid >> 5, lane = tid & 31;
    int lr = lane >> 2, lc = lane & 3;
    int qt = blockIdx.x, h = blockIdx.y, bz = blockIdx.z;

    const float* Q = Qp + bz * sBat + h * sHead + (size_t)qt * 128 * ld;
    const float* K = Kp + bz * sBat + h * sHead;
    const float* V = Vp + bz * sBat + h * sHead;
    const int* mrow = mask + bz * NSEQ;
    float* O = Op + bz * sOb + h * sOh + (size_t)qt * 128 * ldo;

    auto load_kv = [&](int buf, int c) {
#pragma unroll
        for (int i = 0; i < 8; i++) {
            int idx = tid + i * 256, row = idx >> 4, col = idx & 15;
            CP_ASYNC16(sb + KS + buf * TSZ + row * RB + col * 16,
                       K + (size_t)(c * 128 + row) * ld + col * 4);
        }
#pragma unroll
        for (int i = 0; i < 8; i++) {
            int idx = tid + i * 256, row = idx >> 4, col = idx & 15;
            CP_ASYNC16(sb + VS + buf * TSZ + row * RB + col * 16,
                       V + (size_t)(c * 128 + row) * ld + col * 4);
        }
        if (tid < 32)
            CP_ASYNC16(sb + MK + buf * 512 + tid * 16, mrow + c * 128 + tid * 4);
        CP_COMMIT();
    };

    // Q tile + first K/V chunk
#pragma unroll
    for (int i = 0; i < 8; i++) {
        int idx = tid + i * 256, row = idx >> 4, col = idx & 15;
        CP_ASYNC16(sb + row * RB + col * 16, Q + (size_t)row * ld + col * 4);
    }
    CP_COMMIT();
    load_kv(0, 0);
    asm volatile("cp.async.wait_group 0;" ::: "memory");
    __syncthreads();

    // Preload Q fragments (A-frag, m16n8k8 row-major) for all 8 d-steps
    const uint32_t* Qs = (const uint32_t*)smem;
    uint32_t qf[8][4];
    {
        int m0 = w * 16 + lr;
#pragma unroll
        for (int ds = 0; ds < 8; ds++) {
            qf[ds][0] = Qs[m0 * ST + ds * 8 + lc];
            qf[ds][1] = Qs[(m0 + 8) * ST + ds * 8 + lc];
            qf[ds][2] = Qs[m0 * ST + ds * 8 + lc + 4];
            qf[ds][3] = Qs[(m0 + 8) * ST + ds * 8 + lc + 4];
        }
    }

    float o[8][4];
#pragma unroll
    for (int dt = 0; dt < 8; dt++)
        o[dt][0] = o[dt][1] = o[dt][2] = o[dt][3] = 0.f;
    float m0r = -1e30f, m1r = -1e30f, l0 = 0.f, l1 = 0.f;

    for (int c = 0; c < 8; c++) {
        int buf = c & 1;
        asm volatile("cp.async.wait_group 0;" ::: "memory");
        __syncthreads();
        if (c + 1 < 8) load_kv(buf ^ 1, c + 1);

        const uint32_t* Ks = (const uint32_t*)(smem + KS + buf * TSZ);
        const uint32_t* Vs = (const uint32_t*)(smem + VS + buf * TSZ);
        const int* mk = (const int*)(smem + MK + buf * 512);

        // S = Q @ K^T for this 128-key chunk (16 n-tiles of 8)
        float s[16][4];
#pragma unroll
        for (int j = 0; j < 16; j++) {
            s[j][0] = s[j][1] = s[j][2] = s[j][3] = 0.f;
#pragma unroll
            for (int ds = 0; ds < 8; ds++) {
                uint32_t bk[2];
                bk[0] = Ks[(j * 8 + lr) * ST + ds * 8 + lc];
                bk[1] = Ks[(j * 8 + lr) * ST + ds * 8 + lc + 4];
                mma8(s[j], qf[ds], bk);
            }
        }

        // scale + mask, chunk row max
        float mx0 = -1e30f, mx1 = -1e30f;
#pragma unroll
        for (int j = 0; j < 16; j++) {
            float ma0 = (mk[j * 8 + 2 * lc]     == 1) ? 0.f : -10000.f;
            float ma1 = (mk[j * 8 + 2 * lc + 1] == 1) ? 0.f : -10000.f;
            s[j][0] = s[j][0] * 0.125f + ma0;
            s[j][1] = s[j][1] * 0.125f + ma1;
            s[j][2] = s[j][2] * 0.125f + ma0;
            s[j][3] = s[j][3] * 0.125f + ma1;
            mx0 = fmaxf(mx0, fmaxf(s[j][0], s[j][1]));
            mx1 = fmaxf(mx1, fmaxf(s[j][2], s[j][3]));
        }
        mx0 = fmaxf(mx0, __shfl_xor_sync(0xffffffffu, mx0, 1));
        mx0 = fmaxf(mx0, __shfl_xor_sync(0xffffffffu, mx0, 2));
        mx1 = fmaxf(mx1, __shfl_xor_sync(0xffffffffu, mx1, 1));
        mx1 = fmaxf(mx1, __shfl_xor_sync(0xffffffffu, mx1, 2));

        float mn0 = fmaxf(m0r, mx0), mn1 = fmaxf(m1r, mx1);
        float al0 = __expf(m0r - mn0), al1 = __expf(m1r - mn1);
        m0r = mn0; m1r = mn1;

        // P = exp(S - m), rounded to tf32; partial row sums
        float r0 = 0.f, r1 = 0.f;
#pragma unroll
        for (int j = 0; j < 16; j++) {
            s[j][0] = rnd_tf32(__expf(s[j][0] - m0r));
            s[j][1] = rnd_tf32(__expf(s[j][1] - m0r));
            s[j][2] = rnd_tf32(__expf(s[j][2] - m1r));
            s[j][3] = rnd_tf32(__expf(s[j][3] - m1r));
            r0 += s[j][0] + s[j][1];
            r1 += s[j][2] + s[j][3];
        }
        l0 = l0 * al0 + r0;
        l1 = l1 * al1 + r1;

        // rescale O
#pragma unroll
        for (int dt = 0; dt < 8; dt++) {
            o[dt][0] *= al0; o[dt][1] *= al0;
            o[dt][2] *= al1; o[dt][3] *= al1;
        }

        // O += P @ V : convert P C-frag -> A-frag via quad shuffles, then mma
        int base = lane & ~3;
        int src0 = base + (lc >> 1), src1 = src0 + 2;
        bool odd = lc & 1;
#pragma unroll
        for (int kb = 0; kb < 16; kb++) {
            float v00 = __shfl_sync(0xffffffffu, s[kb][0], src0);
            float v01 = __shfl_sync(0xffffffffu, s[kb][1], src0);
            float v02 = __shfl_sync(0xffffffffu, s[kb][0], src1);
            float v03 = __shfl_sync(0xffffffffu, s[kb][1], src1);
            float v10 = __shfl_sync(0xffffffffu, s[kb][2], src0);
            float v11 = __shfl_sync(0xffffffffu, s[kb][3], src0);
            float v12 = __shfl_sync(0xffffffffu, s[kb][2], src1);
            float v13 = __shfl_sync(0xffffffffu, s[kb][3], src1);
            uint32_t aP[4];
            aP[0] = __float_as_uint(odd ? v01 : v00);
            aP[1] = __float_as_uint(odd ? v11 : v10);
            aP[2] = __float_as_uint(odd ? v03 : v02);
            aP[3] = __float_as_uint(odd ? v13 : v12);
#pragma unroll
            for (int dt = 0; dt < 8; dt++) {
                uint32_t bv[2];
                bv[0] = Vs[(kb * 8 + lc) * ST + dt * 8 + lr];
                bv[1] = Vs[(kb * 8 + lc + 4) * ST + dt * 8 + lr];
                mma8(o[dt], aP, bv);
            }
        }
    }

    // finalize: row sums across quad, normalize, round, store
    l0 += __shfl_xor_sync(0xffffffffu, l0, 1);
    l0 += __shfl_xor_sync(0xffffffffu, l0, 2);
    l1 += __shfl_xor_sync(0xffffffffu, l1, 1);
    l1 += __shfl_xor_sync(0xffffffffu, l1, 2);
    float inv0 = 1.f / l0, inv1 = 1.f / l1;
    int row0 = w * 16 + lr, row1 = row0 + 8;
#pragma unroll
    for (int dt = 0; dt < 8; dt++) {
        int col = dt * 8 + 2 * lc;
        float2 v0 = make_float2(rnd_tf32(o[dt][0] * inv0), rnd_tf32(o[dt][1] * inv0));
        float2 v1 = make_float2(rnd_tf32(o[dt][2] * inv1), rnd_tf32(o[dt][3] * inv1));
        *(float2*)(O + (size_t)row0 * ldo + col) = v0;
        *(float2*)(O + (size_t)row1 * ldo + col) = v1;
    }
}

// ---------------------------------------------------------------------------
// tf32 mma.sync GEMM (round-4 proven config). C = A @ B^T (+bias/GELU/res/rnd)
// BM=128, BK=32, 256 thr, 8 warps (2x4), warp tile 64x32. 2-stage cp.async.
// mode: bit0 = GELU, bit1 = round output to tf32.
// ---------------------------------------------------------------------------
template <int BN>
__global__ void __launch_bounds__(256, 2)
mm_mma(const float* __restrict__ A, const float* __restrict__ B,
       const float* __restrict__ bias, const float* __restrict__ res,
       float* __restrict__ C, int K, int lda, int ldb, int ldc, int mode) {
    constexpr int BM = 128, BK = 32, AST = BK + 4;
    constexpr int ABYTES = BM * AST * 4;
    constexpr int BBYTES = BN * AST * 4;
    constexpr int WN = BN / 4;
    constexpr int NT = WN / 8;
    constexpr int MT = 4;

    extern __shared__ char smem[];
    uint32_t sb = smem_u32(smem);
    uint32_t sA[2] = { sb, sb + ABYTES };
    uint32_t sB[2] = { sb + 2 * ABYTES, sb + 2 * ABYTES + BBYTES };

    int tid = threadIdx.x;
    int wid = tid >> 5, lane = tid & 31;
    int warpM = wid >> 2, warpN = wid & 3;
    int lr = lane >> 2, lc = lane & 3;

    int rowBase = blockIdx.y * BM;
    int colBase = blockIdx.x * BN;

    float acc[MT][NT][4];
#pragma unroll
    for (int i = 0; i < MT; i++)
#pragma unroll
        for (int j = 0; j < NT; j++)
#pragma unroll
            for (int q = 0; q < 4; q++) acc[i][j][q] = 0.f;

    auto load_stage = [&](int buf, int k0) {
#pragma unroll
        for (int i = 0; i < (BM * 8) / 256; i++) {
            int idx = tid + i * 256;
            int row = idx >> 3, c = idx & 7;
            uint32_t dst = sA[buf] + (uint32_t)(row * (AST * 4) + c * 16);
            const float* src = A + (size_t)(rowBase + row) * lda + k0 + c * 4;
            CP_ASYNC16(dst, src);
        }
#pragma unroll
        for (int i = 0; i < (BN * 8) / 256; i++) {
            int idx = tid + i * 256;
            int row = idx >> 3, c = idx & 7;
            uint32_t dst = sB[buf] + (uint32_t)(row * (AST * 4) + c * 16);
            const float* src = B + (size_t)(colBase + row) * ldb + k0 + c * 4;
            CP_ASYNC16(dst, src);
        }
        CP_COMMIT();
    };

    int nsteps = K / BK;
    load_stage(0, 0);
    load_stage(1, BK);

    for (int s = 0; s < nsteps; s++) {
        int buf = s & 1;
        if (s + 1 < nsteps) asm volatile("cp.async.wait_group 1;" ::: "memory");
        else                asm volatile("cp.async.wait_group 0;" ::: "memory");
        __syncthreads();

        const uint32_t* As = (const uint32_t*)(smem + (sA[buf] - sb));
        const uint32_t* Bs = (const uint32_t*)(smem + (sB[buf] - sb));
#pragma unroll
        for (int kk = 0; kk < BK; kk += 8) {
            uint32_t af[MT][4], bf[NT][2];
#pragma unroll
            for (int i = 0; i < MT; i++) {
                int m0 = warpM * 64 + i * 16 + lr;
                int k = kk + lc;
                af[i][0] = As[m0 * AST + k];
                af[i][1] = As[(m0 + 8) * AST + k];
                af[i][2] = As[m0 * AST + k + 4];
                af[i][3] = As[(m0 + 8) * AST + k + 4];
            }
#pragma unroll
            for (int j = 0; j < NT; j++) {
                int n0 = warpN * WN + j * 8 + lr;
                int k = kk + lc;
                bf[j][0] = Bs[n0 * AST + k];
                bf[j][1] = Bs[n0 * AST + k + 4];
            }
#pragma unroll
            for (int i = 0; i < MT; i++)
#pragma unroll
                for (int j = 0; j < NT; j++)
                    mma8(acc[i][j], af[i], bf[j]);
        }
        __syncthreads();
        if (s + 2 < nsteps) load_stage(buf, (s + 2) * BK);
    }

    bool gelu = mode & 1, rnd = mode & 2;
#pragma unroll
    for (int i = 0; i < MT; i++) {
#pragma unroll
        for (int j = 0; j < NT; j++) {
#pragma unroll
            for (int h = 0; h < 2; h++) {
                int r = rowBase + warpM * 64 + i * 16 + lr + h * 8;
                int cb = colBase + warpN * WN + j * 8 + lc * 2;
                float v0 = acc[i][j][h * 2 + 0];
                float v1 = acc[i][j][h * 2 + 1];
                if (bias) { v0 += bias[cb]; v1 += bias[cb + 1]; }
                if (gelu) {
                    v0 = 0.5f * v0 * (1.f + erff(v0 * 0.70710678118654752f));
                    v1 = 0.5f * v1 * (1.f + erff(v1 * 0.70710678118654752f));
                }
                if (rnd) { v0 = rnd_tf32(v0); v1 = rnd_tf32(v1); }
                size_t off = (size_t)r * ldc + cb;
                if (res) {
                    float2 rv = *(const float2*)(res + off);
                    v0 += rv.x; v1 += rv.y;
                }
                *(float2*)(C + off) = make_float2(v0, v1);
            }
        }
    }
}

// ---------------------------------------------------------------------------
// Host-side launch orchestration
// ---------------------------------------------------------------------------
extern "C" void kernel_launch(void* const* d_in, const int* in_sizes, int n_in,
                              void* d_out, int out_size) {
    const float* x_in     = (const float*)d_in[0];
    const float* c_in     = (const float*)d_in[1];
    const int*   mask     = (const int*)d_in[2];
    const float* sa_qkv_w = (const float*)d_in[3];
    const float* sa_qkv_b = (const float*)d_in[4];
    const float* sa_proj_w= (const float*)d_in[5];
    const float* sa_proj_b= (const float*)d_in[6];
    const float* ca_q_w   = (const float*)d_in[7];
    const float* ca_q_b   = (const float*)d_in[8];
    const float* ca_k_w   = (const float*)d_in[9];
    const float* ca_k_b   = (const float*)d_in[10];
    const float* ca_v_w   = (const float*)d_in[11];
    const float* ca_v_b   = (const float*)d_in[12];
    const float* ca_proj_w= (const float*)d_in[13];
    const float* ca_proj_b= (const float*)d_in[14];
    const float* fc1_w    = (const float*)d_in[15];
    const float* fc1_b    = (const float*)d_in[16];
    const float* fc2_w    = (const float*)d_in[17];
    const float* fc2_b    = (const float*)d_in[18];

    float* xb = (float*)d_out;

    float *gh, *gqkv, *gattn, *gmlp, *gwt;
    cudaGetSymbolAddress((void**)&gh,    g_h);
    cudaGetSymbolAddress((void**)&gqkv,  g_qkv);
    cudaGetSymbolAddress((void**)&gattn, g_attn);
    cudaGetSymbolAddress((void**)&gmlp,  g_mlp);
    cudaGetSymbolAddress((void**)&gwt,   g_wt);

    const int AST4 = (32 + 4) * 4;
    const int SMEM128 = 2 * 128 * AST4 + 2 * 128 * AST4;   // 73728
    const int SMEM_FLASH = 5 * (128 * 68 * 4) + 2 * 512;   // 175104
    cudaFuncSetAttribute(mm_mma<128>, cudaFuncAttributeMaxDynamicSharedMemorySize, SMEM128);
    cudaFuncSetAttribute(flash_kernel, cudaFuncAttributeMaxDynamicSharedMemorySize, SMEM_FLASH);

    dim3 tblock(32, 8);
    dim3 fgrid(NSEQ / 128, HEADS, NBAT);

    cudaMemcpyAsync(xb, x_in, (size_t)TOK * CDIM * sizeof(float),
                    cudaMemcpyDeviceToDevice, 0);

    // ===================== self-attention =====================
    ln_kernel<<<TOK, 256>>>(xb, gh);

    transpose_kernel<<<dim3(3072/32, 1024/32), tblock>>>(sa_qkv_w, gwt, 3072, 1024);
    mm_mma<128><<<dim3(3072/128, TOK/128), 256, SMEM128>>>(
        gh, gwt, sa_qkv_b, nullptr, gqkv, 1024, 1024, 1024, 3072, 2);

    // fused attention: Q/K/V K-major inside gqkv, ld=3072
    flash_kernel<<<fgrid, 256, SMEM_FLASH>>>(
        gqkv, gqkv + CDIM, gqkv + 2 * CDIM, mask, gattn, 3072, 1024,
        (long long)NSEQ * 3 * CDIM, (long long)HD,
        (long long)NSEQ * CDIM, (long long)HD);

    transpose_kernel<<<dim3(1024/32, 1024/32), tblock>>>(sa_proj_w, gwt, 1024, 1024);
    mm_mma<128><<<dim3(CDIM/128, TOK/128), 256, SMEM128>>>(
        gattn, gwt, sa_proj_b, xb, xb, 1024, 1024, 1024, 1024, 0);

    // ===================== cross-attention =====================
    ln_kernel<<<TOK, 256>>>(xb, gh);

    float* gq = gqkv;
    float* gk = gqkv + (size_t)TOK * CDIM;
    float* gv = gqkv + (size_t)2 * TOK * CDIM;
    float* gcr = gmlp;   // gmlp free until MLP phase: rounded copy of c

    round_copy<<<TOK * CDIM / 4 / 256, 256>>>(c_in, gcr);

    transpose_kernel<<<dim3(1024/32, 1024/32), tblock>>>(ca_q_w, gwt, 1024, 1024);
    mm_mma<128><<<dim3(CDIM/128, TOK/128), 256, SMEM128>>>(
        gh, gwt, ca_q_b, nullptr, gq, 1024, 1024, 1024, 1024, 2);
    transpose_kernel<<<dim3(1024/32, 1024/32), tblock>>>(ca_k_w, gwt, 1024, 1024);
    mm_mma<128><<<dim3(CDIM/128, TOK/128), 256, SMEM128>>>(
        gcr, gwt, ca_k_b, nullptr, gk, 1024, 1024, 1024, 1024, 2);
    transpose_kernel<<<dim3(1024/32, 1024/32), tblock>>>(ca_v_w, gwt, 1024, 1024);
    mm_mma<128><<<dim3(CDIM/128, TOK/128), 256, SMEM128>>>(
        gcr, gwt, ca_v_b, nullptr, gv, 1024, 1024, 1024, 1024, 2);

    flash_kernel<<<fgrid, 256, SMEM_FLASH>>>(
        gq, gk, gv, mask, gattn, 1024, 1024,
        (long long)NSEQ * CDIM, (long long)HD,
        (long long)NSEQ * CDIM, (long long)HD);

    transpose_kernel<<<dim3(1024/32, 1024/32), tblock>>>(ca_proj_w, gwt, 1024, 1024);
    mm_mma<128><<<dim3(CDIM/128, TOK/128), 256, SMEM128>>>(
        gattn, gwt, ca_proj_b, xb, xb, 1024, 1024, 1024, 1024, 0);

    // ===================== MLP =====================
    ln_kernel<<<TOK, 256>>>(xb, gh);

    transpose_kernel<<<dim3(4096/32, 1024/32), tblock>>>(fc1_w, gwt, 4096, 1024);
    mm_mma<128><<<dim3(4096/128, TOK/128), 256, SMEM128>>>(
        gh, gwt, fc1_b, nullptr, gmlp, 1024, 1024, 1024, 4096, 3);

    transpose_kernel<<<dim3(1024/32, 4096/32), tblock>>>(fc2_w, gwt, 1024, 4096);
    mm_mma<128><<<dim3(CDIM/128, TOK/128), 256, SMEM128>>>(
        gmlp, gwt, fc2_b, xb, xb, 4096, 4096, 4096, 1024, 0);
}

// round 9
// speedup vs baseline: 1.3212x; 1.0278x over previous
#include <cuda_runtime.h>
#include <math.h>
#include <stdint.h>

// Problem constants
#define TOK   4096         // B*N
#define CDIM  1024
#define HEADS 16
#define NBAT  4
#define NSEQ  1024
#define HD    64

// Scratch (device globals: allocation-free per harness rules)
__device__ __align__(256) float g_h[TOK * CDIM];                              // 16 MB
__device__ __align__(256) float g_qkv[TOK * 3 * CDIM];                        // 48 MB
__device__ __align__(256) float g_attn[TOK * CDIM];                           // 16 MB
__device__ __align__(256) float g_mlp[TOK * 4 * CDIM];                        // 64 MB (also rounded-c)
__device__ __align__(256) float g_wt[16777216];                               // 64 MB (all transposed weights)

// g_wt float offsets
#define W_QKV    0
#define W_SAPROJ 3145728
#define W_CAQ    4194304
#define W_CAK    5242880
#define W_CAV    6291456
#define W_CAPROJ 7340032
#define W_FC1    8388608
#define W_FC2    12582912

// ---------------------------------------------------------------------------
// Helpers
// ---------------------------------------------------------------------------
__device__ __forceinline__ uint32_t smem_u32(const void* p) {
    uint32_t a;
    asm("{ .reg .u64 t; cvta.to.shared.u64 t, %1; cvt.u32.u64 %0, t; }" : "=r"(a) : "l"(p));
    return a;
}
__device__ __forceinline__ float rnd_tf32(float x) {
    uint32_t u;
    asm("cvt.rna.tf32.f32 %0, %1;" : "=r"(u) : "f"(x));
    return __uint_as_float(u);
}
#define CP_ASYNC16(dst, src) \
    asm volatile("cp.async.cg.shared.global [%0], [%1], 16;" :: "r"(dst), "l"(src) : "memory")
#define CP_COMMIT()  asm volatile("cp.async.commit_group;" ::: "memory")

__device__ __forceinline__ void mma8(float* d, const uint32_t* a, const uint32_t* b) {
    asm volatile("mma.sync.aligned.m16n8k8.row.col.f32.tf32.tf32.f32 "
                 "{%0,%1,%2,%3}, {%4,%5,%6,%7}, {%8,%9}, {%0,%1,%2,%3};"
                 : "+f"(d[0]), "+f"(d[1]), "+f"(d[2]), "+f"(d[3])
                 : "r"(a[0]), "r"(a[1]), "r"(a[2]), "r"(a[3]), "r"(b[0]), "r"(b[1]));
}

// ---------------------------------------------------------------------------
// LayerNorm (no affine, eps=1e-6), rounds output to tf32 (it feeds MMA only)
// ---------------------------------------------------------------------------
__global__ void ln_kernel(const float* __restrict__ in, float* __restrict__ out) {
    __shared__ float sred[256];
    int row = blockIdx.x;
    const float4* p = (const float4*)(in + (size_t)row * CDIM);
    float4 v = p[threadIdx.x];
    float s = v.x + v.y + v.z + v.w;
    sred[threadIdx.x] = s; __syncthreads();
    for (int o = 128; o > 0; o >>= 1) {
        if (threadIdx.x < o) sred[threadIdx.x] += sred[threadIdx.x + o];
        __syncthreads();
    }
    float mean = sred[0] * (1.f / CDIM);
    __syncthreads();
    float dx = v.x-mean, dy = v.y-mean, dz = v.z-mean, dw = v.w-mean;
    sred[threadIdx.x] = dx*dx + dy*dy + dz*dz + dw*dw; __syncthreads();
    for (int o = 128; o > 0; o >>= 1) {
        if (threadIdx.x < o) sred[threadIdx.x] += sred[threadIdx.x + o];
        __syncthreads();
    }
    float inv = rsqrtf(sred[0] * (1.f / CDIM) + 1e-6f);
    float4 r = make_float4(rnd_tf32(dx*inv), rnd_tf32(dy*inv),
                           rnd_tf32(dz*inv), rnd_tf32(dw*inv));
    ((float4*)(out + (size_t)row * CDIM))[threadIdx.x] = r;
}

// ---------------------------------------------------------------------------
// Elementwise round-to-tf32 copy (for raw c input feeding K/V GEMMs)
// ---------------------------------------------------------------------------
__global__ void round_copy(const float* __restrict__ in, float* __restrict__ out) {
    size_t i = (size_t)blockIdx.x * 256 + threadIdx.x;
    float4 v = ((const float4*)in)[i];
    v.x = rnd_tf32(v.x); v.y = rnd_tf32(v.y);
    v.z = rnd_tf32(v.z); v.w = rnd_tf32(v.w);
    ((float4*)out)[i] = v;
}

// ---------------------------------------------------------------------------
// Batched multi-weight 32x32 tiled transpose (all 8 weights, one launch).
// out[c][r] = rnd_tf32(in[r][c]). Segment table passed by value.
// ---------------------------------------------------------------------------
struct TArgs {
    const float* in[8];
    float* out[8];
    int ldin[8];     // = in cols
    int ldout[8];    // = in rows
    int tilesX[8];   // ldin/32
    int tileEnd[8];  // exclusive prefix sum of tile counts
};

__global__ void multi_transpose(TArgs a) {
    __shared__ float t[32][33];
    int bid = blockIdx.x;
    int s = 0;
#pragma unroll
    for (int i = 0; i < 8; i++)
        if (bid >= a.tileEnd[i]) s = i + 1;
    int t0 = s ? a.tileEnd[s - 1] : 0;
    int lt = bid - t0;
    int tx = lt % a.tilesX[s], ty = lt / a.tilesX[s];
    const float* in = a.in[s];
    float* out = a.out[s];
    int ldin = a.ldin[s], ldout = a.ldout[s];
    int c0 = tx * 32, r0 = ty * 32;
    int x = threadIdx.x, y = threadIdx.y;
#pragma unroll
    for (int i = 0; i < 32; i += 8)
        t[y + i][x] = in[(size_t)(r0 + y + i) * ldin + c0 + x];
    __syncthreads();
#pragma unroll
    for (int i = 0; i < 32; i += 8)
        out[(size_t)(c0 + y + i) * ldout + r0 + x] = rnd_tf32(t[x][y + i]);
}

// ---------------------------------------------------------------------------
// Fused flash-attention (tf32 mma.sync), non-causal, additive key mask.
//   Per CTA: 64 query rows of one (batch, head). 128 threads, 4 warps,
//   warp w owns Q rows [16w, 16w+16). K/V streamed in 64-key chunks,
//   double-buffered cp.async. S in regs, online softmax, O in regs.
//   2 CTAs/SM (regs ~180, smem ~87.5KB).
// ---------------------------------------------------------------------------
__global__ void __launch_bounds__(128, 2)
flash_kernel(const float* __restrict__ Qp, const float* __restrict__ Kp,
             const float* __restrict__ Vp, const int* __restrict__ mask,
             float* __restrict__ Op, int ld, int ldo,
             long long sBat, long long sHead, long long sOb, long long sOh) {
    constexpr int ST  = 68;          // floats per smem row (64 + 4 pad)
    constexpr int RB  = ST * 4;      // 272 bytes
    constexpr int TSZ = 64 * RB;     // 17408 bytes per 64-row tile
    const int KS = TSZ;              // K bufs at TSZ, 2*TSZ
    const int VS = TSZ * 3;          // V bufs at 3*TSZ, 4*TSZ
    const int MK = TSZ * 5;          // mask bufs 256B each

    extern __shared__ char smem[];
    uint32_t sb = smem_u32(smem);

    int tid = threadIdx.x, w = tid >> 5, lane = tid & 31;
    int lr = lane >> 2, lc = lane & 3;
    int qt = blockIdx.x, h = blockIdx.y, bz = blockIdx.z;

    const float* Q = Qp + bz * sBat + h * sHead + (size_t)qt * 64 * ld;
    const float* K = Kp + bz * sBat + h * sHead;
    const float* V = Vp + bz * sBat + h * sHead;
    const int* mrow = mask + bz * NSEQ;
    float* O = Op + bz * sOb + h * sOh + (size_t)qt * 64 * ldo;

    auto load_kv = [&](int buf, int c) {
#pragma unroll
        for (int i = 0; i < 8; i++) {
            int idx = tid + i * 128, row = idx >> 4, col = idx & 15;
            CP_ASYNC16(sb + KS + buf * TSZ + row * RB + col * 16,
                       K + (size_t)(c * 64 + row) * ld + col * 4);
        }
#pragma unroll
        for (int i = 0; i < 8; i++) {
            int idx = tid + i * 128, row = idx >> 4, col = idx & 15;
            CP_ASYNC16(sb + VS + buf * TSZ + row * RB + col * 16,
                       V + (size_t)(c * 64 + row) * ld + col * 4);
        }
        if (tid < 16)
            CP_ASYNC16(sb + MK + buf * 256 + tid * 16, mrow + c * 64 + tid * 4);
        CP_COMMIT();
    };

    // Q tile + first K/V chunk
#pragma unroll
    for (int i = 0; i < 8; i++) {
        int idx = tid + i * 128, row = idx >> 4, col = idx & 15;
        CP_ASYNC16(sb + row * RB + col * 16, Q + (size_t)row * ld + col * 4);
    }
    CP_COMMIT();
    load_kv(0, 0);
    asm volatile("cp.async.wait_group 0;" ::: "memory");
    __syncthreads();

    // Preload Q fragments (A-frag, m16n8k8 row-major) for all 8 d-steps
    const uint32_t* Qs = (const uint32_t*)smem;
    uint32_t qf[8][4];
    {
        int m0 = w * 16 + lr;
#pragma unroll
        for (int ds = 0; ds < 8; ds++) {
            qf[ds][0] = Qs[m0 * ST + ds * 8 + lc];
            qf[ds][1] = Qs[(m0 + 8) * ST + ds * 8 + lc];
            qf[ds][2] = Qs[m0 * ST + ds * 8 + lc + 4];
            qf[ds][3] = Qs[(m0 + 8) * ST + ds * 8 + lc + 4];
        }
    }

    float o[8][4];
#pragma unroll
    for (int dt = 0; dt < 8; dt++)
        o[dt][0] = o[dt][1] = o[dt][2] = o[dt][3] = 0.f;
    float m0r = -1e30f, m1r = -1e30f, l0 = 0.f, l1 = 0.f;

    for (int c = 0; c < 16; c++) {
        int buf = c & 1;
        asm volatile("cp.async.wait_group 0;" ::: "memory");
        __syncthreads();
        if (c + 1 < 16) load_kv(buf ^ 1, c + 1);

        const uint32_t* Ks = (const uint32_t*)(smem + KS + buf * TSZ);
        const uint32_t* Vs = (const uint32_t*)(smem + VS + buf * TSZ);
        const int* mk = (const int*)(smem + MK + buf * 256);

        // S = Q @ K^T for this 64-key chunk (8 n-tiles of 8)
        float s[8][4];
#pragma unroll
        for (int j = 0; j < 8; j++) {
            s[j][0] = s[j][1] = s[j][2] = s[j][3] = 0.f;
#pragma unroll
            for (int ds = 0; ds < 8; ds++) {
                uint32_t bk[2];
                bk[0] = Ks[(j * 8 + lr) * ST + ds * 8 + lc];
                bk[1] = Ks[(j * 8 + lr) * ST + ds * 8 + lc + 4];
                mma8(s[j], qf[ds], bk);
            }
        }

        // scale + mask, chunk row max
        float mx0 = -1e30f, mx1 = -1e30f;
#pragma unroll
        for (int j = 0; j < 8; j++) {
            float ma0 = (mk[j * 8 + 2 * lc]     == 1) ? 0.f : -10000.f;
            float ma1 = (mk[j * 8 + 2 * lc + 1] == 1) ? 0.f : -10000.f;
            s[j][0] = s[j][0] * 0.125f + ma0;
            s[j][1] = s[j][1] * 0.125f + ma1;
            s[j][2] = s[j][2] * 0.125f + ma0;
            s[j][3] = s[j][3] * 0.125f + ma1;
            mx0 = fmaxf(mx0, fmaxf(s[j][0], s[j][1]));
            mx1 = fmaxf(mx1, fmaxf(s[j][2], s[j][3]));
        }
        mx0 = fmaxf(mx0, __shfl_xor_sync(0xffffffffu, mx0, 1));
        mx0 = fmaxf(mx0, __shfl_xor_sync(0xffffffffu, mx0, 2));
        mx1 = fmaxf(mx1, __shfl_xor_sync(0xffffffffu, mx1, 1));
        mx1 = fmaxf(mx1, __shfl_xor_sync(0xffffffffu, mx1, 2));

        float mn0 = fmaxf(m0r, mx0), mn1 = fmaxf(m1r, mx1);
        float al0 = __expf(m0r - mn0), al1 = __expf(m1r - mn1);
        m0r = mn0; m1r = mn1;

        // P = exp(S - m), rounded to tf32; partial row sums
        float r0 = 0.f, r1 = 0.f;
#pragma unroll
        for (int j = 0; j < 8; j++) {
            s[j][0] = rnd_tf32(__expf(s[j][0] - m0r));
            s[j][1] = rnd_tf32(__expf(s[j][1] - m0r));
            s[j][2] = rnd_tf32(__expf(s[j][2] - m1r));
            s[j][3] = rnd_tf32(__expf(s[j][3] - m1r));
            r0 += s[j][0] + s[j][1];
            r1 += s[j][2] + s[j][3];
        }
        l0 = l0 * al0 + r0;
        l1 = l1 * al1 + r1;

        // rescale O
#pragma unroll
        for (int dt = 0; dt < 8; dt++) {
            o[dt][0] *= al0; o[dt][1] *= al0;
            o[dt][2] *= al1; o[dt][3] *= al1;
        }

        // O += P @ V : convert P C-frag -> A-frag via quad shuffles, then mma
        int base = lane & ~3;
        int src0 = base + (lc >> 1), src1 = src0 + 2;
        bool odd = lc & 1;
#pragma unroll
        for (int kb = 0; kb < 8; kb++) {
            float v00 = __shfl_sync(0xffffffffu, s[kb][0], src0);
            float v01 = __shfl_sync(0xffffffffu, s[kb][1], src0);
            float v02 = __shfl_sync(0xffffffffu, s[kb][0], src1);
            float v03 = __shfl_sync(0xffffffffu, s[kb][1], src1);
            float v10 = __shfl_sync(0xffffffffu, s[kb][2], src0);
            float v11 = __shfl_sync(0xffffffffu, s[kb][3], src0);
            float v12 = __shfl_sync(0xffffffffu, s[kb][2], src1);
            float v13 = __shfl_sync(0xffffffffu, s[kb][3], src1);
            uint32_t aP[4];
            aP[0] = __float_as_uint(odd ? v01 : v00);
            aP[1] = __float_as_uint(odd ? v11 : v10);
            aP[2] = __float_as_uint(odd ? v03 : v02);
            aP[3] = __float_as_uint(odd ? v13 : v12);
#pragma unroll
            for (int dt = 0; dt < 8; dt++) {
                uint32_t bv[2];
                bv[0] = Vs[(kb * 8 + lc) * ST + dt * 8 + lr];
                bv[1] = Vs[(kb * 8 + lc + 4) * ST + dt * 8 + lr];
                mma8(o[dt], aP, bv);
            }
        }
    }

    // finalize: row sums across quad, normalize, round, store
    l0 += __shfl_xor_sync(0xffffffffu, l0, 1);
    l0 += __shfl_xor_sync(0xffffffffu, l0, 2);
    l1 += __shfl_xor_sync(0xffffffffu, l1, 1);
    l1 += __shfl_xor_sync(0xffffffffu, l1, 2);
    float inv0 = 1.f / l0, inv1 = 1.f / l1;
    int row0 = w * 16 + lr, row1 = row0 + 8;
#pragma unroll
    for (int dt = 0; dt < 8; dt++) {
        int col = dt * 8 + 2 * lc;
        float2 v0 = make_float2(rnd_tf32(o[dt][0] * inv0), rnd_tf32(o[dt][1] * inv0));
        float2 v1 = make_float2(rnd_tf32(o[dt][2] * inv1), rnd_tf32(o[dt][3] * inv1));
        *(float2*)(O + (size_t)row0 * ldo + col) = v0;
        *(float2*)(O + (size_t)row1 * ldo + col) = v1;
    }
}

// ---------------------------------------------------------------------------
// tf32 mma.sync GEMM. C = A @ B^T (+bias/GELU/res/rnd)
// BM=128, BK=32, 256 thr, 8 warps (2x4), warp tile 64x32. 3-stage cp.async.
// mode: bit0 = GELU, bit1 = round output to tf32.
// ---------------------------------------------------------------------------
template <int BN>
__global__ void __launch_bounds__(256, 2)
mm_mma(const float* __restrict__ A, const float* __restrict__ B,
       const float* __restrict__ bias, const float* __restrict__ res,
       float* __restrict__ C, int K, int lda, int ldb, int ldc, int mode) {
    constexpr int BM = 128, BK = 32, AST = BK + 4;
    constexpr int ABYTES = BM * AST * 4;
    constexpr int BBYTES = BN * AST * 4;
    constexpr int WN = BN / 4;
    constexpr int NT = WN / 8;
    constexpr int MT = 4;

    extern __shared__ char smem[];
    uint32_t sb = smem_u32(smem);
    uint32_t aoff[3] = { 0u, (uint32_t)(ABYTES + BBYTES), 2u * (ABYTES + BBYTES) };
    uint32_t boff[3] = { (uint32_t)ABYTES, (uint32_t)(2 * ABYTES + BBYTES),
                         (uint32_t)(3 * ABYTES + 2 * BBYTES) };

    int tid = threadIdx.x;
    int wid = tid >> 5, lane = tid & 31;
    int warpM = wid >> 2, warpN = wid & 3;
    int lr = lane >> 2, lc = lane & 3;

    int rowBase = blockIdx.y * BM;
    int colBase = blockIdx.x * BN;

    float acc[MT][NT][4];
#pragma unroll
    for (int i = 0; i < MT; i++)
#pragma unroll
        for (int j = 0; j < NT; j++)
#pragma unroll
            for (int q = 0; q < 4; q++) acc[i][j][q] = 0.f;

    auto load_stage = [&](int buf, int k0) {
#pragma unroll
        for (int i = 0; i < (BM * 8) / 256; i++) {
            int idx = tid + i * 256;
            int row = idx >> 3, c = idx & 7;
            uint32_t dst = sb + aoff[buf] + (uint32_t)(row * (AST * 4) + c * 16);
            const float* src = A + (size_t)(rowBase + row) * lda + k0 + c * 4;
            CP_ASYNC16(dst, src);
        }
#pragma unroll
        for (int i = 0; i < (BN * 8) / 256; i++) {
            int idx = tid + i * 256;
            int row = idx >> 3, c = idx & 7;
            uint32_t dst = sb + boff[buf] + (uint32_t)(row * (AST * 4) + c * 16);
            const float* src = B + (size_t)(colBase + row) * ldb + k0 + c * 4;
            CP_ASYNC16(dst, src);
        }
        CP_COMMIT();
    };

    int nsteps = K / BK;
    load_stage(0, 0);
    load_stage(1, BK);
    load_stage(2, 2 * BK);

    for (int s = 0; s < nsteps; s++) {
        int buf = s % 3;
        int rem = nsteps - 1 - s;
        if (rem >= 2)      asm volatile("cp.async.wait_group 2;" ::: "memory");
        else if (rem == 1) asm volatile("cp.async.wait_group 1;" ::: "memory");
        else               asm volatile("cp.async.wait_group 0;" ::: "memory");
        __syncthreads();

        const uint32_t* As = (const uint32_t*)(smem + aoff[buf]);
        const uint32_t* Bs = (const uint32_t*)(smem + boff[buf]);
#pragma unroll
        for (int kk = 0; kk < BK; kk += 8) {
            uint32_t af[MT][4], bf[NT][2];
#pragma unroll
            for (int i = 0; i < MT; i++) {
                int m0 = warpM * 64 + i * 16 + lr;
                int k = kk + lc;
                af[i][0] = As[m0 * AST + k];
                af[i][1] = As[(m0 + 8) * AST + k];
                af[i][2] = As[m0 * AST + k + 4];
                af[i][3] = As[(m0 + 8) * AST + k + 4];
            }
#pragma unroll
            for (int j = 0; j < NT; j++) {
                int n0 = warpN * WN + j * 8 + lr;
                int k = kk + lc;
                bf[j][0] = Bs[n0 * AST + k];
                bf[j][1] = Bs[n0 * AST + k + 4];
            }
#pragma unroll
            for (int i = 0; i < MT; i++)
#pragma unroll
                for (int j = 0; j < NT; j++)
                    mma8(acc[i][j], af[i], bf[j]);
        }
        __syncthreads();
        if (s + 3 < nsteps) load_stage(buf, (s + 3) * BK);
    }

    bool gelu = mode & 1, rnd = mode & 2;
#pragma unroll
    for (int i = 0; i < MT; i++) {
#pragma unroll
        for (int j = 0; j < NT; j++) {
#pragma unroll
            for (int h = 0; h < 2; h++) {
                int r = rowBase + warpM * 64 + i * 16 + lr + h * 8;
                int cb = colBase + warpN * WN + j * 8 + lc * 2;
                float v0 = acc[i][j][h * 2 + 0];
                float v1 = acc[i][j][h * 2 + 1];
                if (bias) { v0 += bias[cb]; v1 += bias[cb + 1]; }
                if (gelu) {
                    v0 = 0.5f * v0 * (1.f + erff(v0 * 0.70710678118654752f));
                    v1 = 0.5f * v1 * (1.f + erff(v1 * 0.70710678118654752f));
                }
                if (rnd) { v0 = rnd_tf32(v0); v1 = rnd_tf32(v1); }
                size_t off = (size_t)r * ldc + cb;
                if (res) {
                    float2 rv = *(const float2*)(res + off);
                    v0 += rv.x; v1 += rv.y;
                }
                *(float2*)(C + off) = make_float2(v0, v1);
            }
        }
    }
}

// ---------------------------------------------------------------------------
// Host-side launch orchestration
// ---------------------------------------------------------------------------
extern "C" void kernel_launch(void* const* d_in, const int* in_sizes, int n_in,
                              void* d_out, int out_size) {
    const float* x_in     = (const float*)d_in[0];
    const float* c_in     = (const float*)d_in[1];
    const int*   mask     = (const int*)d_in[2];
    const float* sa_qkv_w = (const float*)d_in[3];
    const float* sa_qkv_b = (const float*)d_in[4];
    const float* sa_proj_w= (const float*)d_in[5];
    const float* sa_proj_b= (const float*)d_in[6];
    const float* ca_q_w   = (const float*)d_in[7];
    const float* ca_q_b   = (const float*)d_in[8];
    const float* ca_k_w   = (const float*)d_in[9];
    const float* ca_k_b   = (const float*)d_in[10];
    const float* ca_v_w   = (const float*)d_in[11];
    const float* ca_v_b   = (const float*)d_in[12];
    const float* ca_proj_w= (const float*)d_in[13];
    const float* ca_proj_b= (const float*)d_in[14];
    const float* fc1_w    = (const float*)d_in[15];
    const float* fc1_b    = (const float*)d_in[16];
    const float* fc2_w    = (const float*)d_in[17];
    const float* fc2_b    = (const float*)d_in[18];

    float* xb = (float*)d_out;

    float *gh, *gqkv, *gattn, *gmlp, *gwt;
    cudaGetSymbolAddress((void**)&gh,    g_h);
    cudaGetSymbolAddress((void**)&gqkv,  g_qkv);
    cudaGetSymbolAddress((void**)&gattn, g_attn);
    cudaGetSymbolAddress((void**)&gmlp,  g_mlp);
    cudaGetSymbolAddress((void**)&gwt,   g_wt);

    const int AST4 = (32 + 4) * 4;
    const int SMEM128 = 3 * (128 * AST4 + 128 * AST4);     // 110592
    const int SMEM_FLASH = 5 * (64 * 68 * 4) + 2 * 256;    // 87552
    cudaFuncSetAttribute(mm_mma<128>, cudaFuncAttributeMaxDynamicSharedMemorySize, SMEM128);
    cudaFuncSetAttribute(flash_kernel, cudaFuncAttributeMaxDynamicSharedMemorySize, SMEM_FLASH);

    dim3 tblock(32, 8);
    dim3 fgrid(NSEQ / 64, HEADS, NBAT);

    // ---- batched weight transposes (one launch, start of graph) ----
    TArgs ta;
    const float* wins[8] = { sa_qkv_w, sa_proj_w, ca_q_w, ca_k_w,
                             ca_v_w, ca_proj_w, fc1_w, fc2_w };
    float* wouts[8] = { gwt + W_QKV, gwt + W_SAPROJ, gwt + W_CAQ, gwt + W_CAK,
                        gwt + W_CAV, gwt + W_CAPROJ, gwt + W_FC1, gwt + W_FC2 };
    int rows[8] = { 1024, 1024, 1024, 1024, 1024, 1024, 1024, 4096 };
    int cols[8] = { 3072, 1024, 1024, 1024, 1024, 1024, 4096, 1024 };
    int acc_t = 0;
    for (int i = 0; i < 8; i++) {
        ta.in[i] = wins[i]; ta.out[i] = wouts[i];
        ta.ldin[i] = cols[i]; ta.ldout[i] = rows[i];
        ta.tilesX[i] = cols[i] / 32;
        acc_t += (rows[i] / 32) * (cols[i] / 32);
        ta.tileEnd[i] = acc_t;
    }

    cudaMemcpyAsync(xb, x_in, (size_t)TOK * CDIM * sizeof(float),
                    cudaMemcpyDeviceToDevice, 0);
    multi_transpose<<<acc_t, tblock>>>(ta);
    round_copy<<<TOK * CDIM / 4 / 256, 256>>>(c_in, gmlp);  // rounded c (gmlp free until MLP)

    // ===================== self-attention =====================
    ln_kernel<<<TOK, 256>>>(xb, gh);

    mm_mma<128><<<dim3(3072/128, TOK/128), 256, SMEM128>>>(
        gh, gwt + W_QKV, sa_qkv_b, nullptr, gqkv, 1024, 1024, 1024, 3072, 2);

    flash_kernel<<<fgrid, 128, SMEM_FLASH>>>(
        gqkv, gqkv + CDIM, gqkv + 2 * CDIM, mask, gattn, 3072, 1024,
        (long long)NSEQ * 3 * CDIM, (long long)HD,
        (long long)NSEQ * CDIM, (long long)HD);

    mm_mma<128><<<dim3(CDIM/128, TOK/128), 256, SMEM128>>>(
        gattn, gwt + W_SAPROJ, sa_proj_b, xb, xb, 1024, 1024, 1024, 1024, 0);

    // ===================== cross-attention =====================
    ln_kernel<<<TOK, 256>>>(xb, gh);

    float* gq = gqkv;
    float* gk = gqkv + (size_t)TOK * CDIM;
    float* gv = gqkv + (size_t)2 * TOK * CDIM;
    float* gcr = gmlp;

    mm_mma<128><<<dim3(CDIM/128, TOK/128), 256, SMEM128>>>(
        gh, gwt + W_CAQ, ca_q_b, nullptr, gq, 1024, 1024, 1024, 1024, 2);
    mm_mma<128><<<dim3(CDIM/128, TOK/128), 256, SMEM128>>>(
        gcr, gwt + W_CAK, ca_k_b, nullptr, gk, 1024, 1024, 1024, 1024, 2);
    mm_mma<128><<<dim3(CDIM/128, TOK/128), 256, SMEM128>>>(
        gcr, gwt + W_CAV, ca_v_b, nullptr, gv, 1024, 1024, 1024, 1024, 2);

    flash_kernel<<<fgrid, 128, SMEM_FLASH>>>(
        gq, gk, gv, mask, gattn, 1024, 1024,
        (long long)NSEQ * CDIM, (long long)HD,
        (long long)NSEQ * CDIM, (long long)HD);

    mm_mma<128><<<dim3(CDIM/128, TOK/128), 256, SMEM128>>>(
        gattn, gwt + W_CAPROJ, ca_proj_b, xb, xb, 1024, 1024, 1024, 1024, 0);

    // ===================== MLP =====================
    ln_kernel<<<TOK, 256>>>(xb, gh);

    mm_mma<128><<<dim3(4096/128, TOK/128), 256, SMEM128>>>(
        gh, gwt + W_FC1, fc1_b, nullptr, gmlp, 1024, 1024, 1024, 4096, 3);

    mm_mma<128><<<dim3(CDIM/128, TOK/128), 256, SMEM128>>>(
        gmlp, gwt + W_FC2, fc2_b, xb, xb, 4096, 4096, 4096, 1024, 0);
}

// round 10
// speedup vs baseline: 1.3761x; 1.0415x over previous
#include <cuda_runtime.h>
#include <math.h>
#include <stdint.h>

// Problem constants
#define TOK   4096         // B*N
#define CDIM  1024
#define HEADS 16
#define NBAT  4
#define NSEQ  1024
#define HD    64

// Scratch (device globals: allocation-free per harness rules)
__device__ __align__(256) float g_h[TOK * CDIM];                              // 16 MB
__device__ __align__(256) float g_qkv[TOK * 3 * CDIM];                        // 48 MB (also q + interleaved kv)
__device__ __align__(256) float g_attn[TOK * CDIM];                           // 16 MB
__device__ __align__(256) float g_mlp[TOK * 4 * CDIM];                        // 64 MB (also rounded-c)
__device__ __align__(256) float g_wt[16777216];                               // 64 MB (all transposed weights)
__device__ __align__(256) float g_bias[2048];                                 // concat ca_k_b || ca_v_b

// g_wt float offsets
#define W_QKV    0
#define W_SAPROJ 3145728
#define W_CAQ    4194304
#define W_CAK    5242880
#define W_CAV    6291456
#define W_CAPROJ 7340032
#define W_FC1    8388608
#define W_FC2    12582912

// ---------------------------------------------------------------------------
// Helpers
// ---------------------------------------------------------------------------
__device__ __forceinline__ uint32_t smem_u32(const void* p) {
    uint32_t a;
    asm("{ .reg .u64 t; cvta.to.shared.u64 t, %1; cvt.u32.u64 %0, t; }" : "=r"(a) : "l"(p));
    return a;
}
__device__ __forceinline__ float rnd_tf32(float x) {
    uint32_t u;
    asm("cvt.rna.tf32.f32 %0, %1;" : "=r"(u) : "f"(x));
    return __uint_as_float(u);
}
#define CP_ASYNC16(dst, src) \
    asm volatile("cp.async.cg.shared.global [%0], [%1], 16;" :: "r"(dst), "l"(src) : "memory")
#define CP_COMMIT()  asm volatile("cp.async.commit_group;" ::: "memory")

__device__ __forceinline__ void mma8(float* d, const uint32_t* a, const uint32_t* b) {
    asm volatile("mma.sync.aligned.m16n8k8.row.col.f32.tf32.tf32.f32 "
                 "{%0,%1,%2,%3}, {%4,%5,%6,%7}, {%8,%9}, {%0,%1,%2,%3};"
                 : "+f"(d[0]), "+f"(d[1]), "+f"(d[2]), "+f"(d[3])
                 : "r"(a[0]), "r"(a[1]), "r"(a[2]), "r"(a[3]), "r"(b[0]), "r"(b[1]));
}

// ---------------------------------------------------------------------------
// LayerNorm (no affine, eps=1e-6), rounds output to tf32 (it feeds MMA only)
// ---------------------------------------------------------------------------
__global__ void ln_kernel(const float* __restrict__ in, float* __restrict__ out) {
    __shared__ float sred[256];
    int row = blockIdx.x;
    const float4* p = (const float4*)(in + (size_t)row * CDIM);
    float4 v = p[threadIdx.x];
    float s = v.x + v.y + v.z + v.w;
    sred[threadIdx.x] = s; __syncthreads();
    for (int o = 128; o > 0; o >>= 1) {
        if (threadIdx.x < o) sred[threadIdx.x] += sred[threadIdx.x + o];
        __syncthreads();
    }
    float mean = sred[0] * (1.f / CDIM);
    __syncthreads();
    float dx = v.x-mean, dy = v.y-mean, dz = v.z-mean, dw = v.w-mean;
    sred[threadIdx.x] = dx*dx + dy*dy + dz*dz + dw*dw; __syncthreads();
    for (int o = 128; o > 0; o >>= 1) {
        if (threadIdx.x < o) sred[threadIdx.x] += sred[threadIdx.x + o];
        __syncthreads();
    }
    float inv = rsqrtf(sred[0] * (1.f / CDIM) + 1e-6f);
    float4 r = make_float4(rnd_tf32(dx*inv), rnd_tf32(dy*inv),
                           rnd_tf32(dz*inv), rnd_tf32(dw*inv));
    ((float4*)(out + (size_t)row * CDIM))[threadIdx.x] = r;
}

// ---------------------------------------------------------------------------
// Elementwise round-to-tf32 copy (for raw c input feeding K/V GEMMs)
// ---------------------------------------------------------------------------
__global__ void round_copy(const float* __restrict__ in, float* __restrict__ out) {
    size_t i = (size_t)blockIdx.x * 256 + threadIdx.x;
    float4 v = ((const float4*)in)[i];
    v.x = rnd_tf32(v.x); v.y = rnd_tf32(v.y);
    v.z = rnd_tf32(v.z); v.w = rnd_tf32(v.w);
    ((float4*)out)[i] = v;
}

// ---------------------------------------------------------------------------
// Batched multi-weight 32x32 tiled transpose (all 8 weights, one launch).
// ---------------------------------------------------------------------------
struct TArgs {
    const float* in[8];
    float* out[8];
    int ldin[8];
    int ldout[8];
    int tilesX[8];
    int tileEnd[8];
};

__global__ void multi_transpose(TArgs a) {
    __shared__ float t[32][33];
    int bid = blockIdx.x;
    int s = 0;
#pragma unroll
    for (int i = 0; i < 8; i++)
        if (bid >= a.tileEnd[i]) s = i + 1;
    int t0 = s ? a.tileEnd[s - 1] : 0;
    int lt = bid - t0;
    int tx = lt % a.tilesX[s], ty = lt / a.tilesX[s];
    const float* in = a.in[s];
    float* out = a.out[s];
    int ldin = a.ldin[s], ldout = a.ldout[s];
    int c0 = tx * 32, r0 = ty * 32;
    int x = threadIdx.x, y = threadIdx.y;
#pragma unroll
    for (int i = 0; i < 32; i += 8)
        t[y + i][x] = in[(size_t)(r0 + y + i) * ldin + c0 + x];
    __syncthreads();
#pragma unroll
    for (int i = 0; i < 32; i += 8)
        out[(size_t)(c0 + y + i) * ldout + r0 + x] = rnd_tf32(t[x][y + i]);
}

// ---------------------------------------------------------------------------
// Fused flash-attention (tf32 mma.sync), non-causal, additive key mask.
//   Per CTA: 64 query rows of one (batch, head). 128 threads, 4 warps.
//   Separate Q vs K/V leading dims + batch strides (for interleaved KV).
// ---------------------------------------------------------------------------
__global__ void __launch_bounds__(128, 2)
flash_kernel(const float* __restrict__ Qp, const float* __restrict__ Kp,
             const float* __restrict__ Vp, const int* __restrict__ mask,
             float* __restrict__ Op, int ldq, int ldkv, int ldo,
             long long sQb, long long sKb, long long sOb) {
    constexpr int ST  = 68;          // floats per smem row (64 + 4 pad)
    constexpr int RB  = ST * 4;      // 272 bytes
    constexpr int TSZ = 64 * RB;     // 17408 bytes per 64-row tile
    const int KS = TSZ;
    const int VS = TSZ * 3;
    const int MK = TSZ * 5;

    extern __shared__ char smem[];
    uint32_t sb = smem_u32(smem);

    int tid = threadIdx.x, w = tid >> 5, lane = tid & 31;
    int lr = lane >> 2, lc = lane & 3;
    int qt = blockIdx.x, h = blockIdx.y, bz = blockIdx.z;

    const float* Q = Qp + bz * sQb + (size_t)h * HD + (size_t)qt * 64 * ldq;
    const float* K = Kp + bz * sKb + (size_t)h * HD;
    const float* V = Vp + bz * sKb + (size_t)h * HD;
    const int* mrow = mask + bz * NSEQ;
    float* O = Op + bz * sOb + (size_t)h * HD + (size_t)qt * 64 * ldo;

    auto load_kv = [&](int buf, int c) {
#pragma unroll
        for (int i = 0; i < 8; i++) {
            int idx = tid + i * 128, row = idx >> 4, col = idx & 15;
            CP_ASYNC16(sb + KS + buf * TSZ + row * RB + col * 16,
                       K + (size_t)(c * 64 + row) * ldkv + col * 4);
        }
#pragma unroll
        for (int i = 0; i < 8; i++) {
            int idx = tid + i * 128, row = idx >> 4, col = idx & 15;
            CP_ASYNC16(sb + VS + buf * TSZ + row * RB + col * 16,
                       V + (size_t)(c * 64 + row) * ldkv + col * 4);
        }
        if (tid < 16)
            CP_ASYNC16(sb + MK + buf * 256 + tid * 16, mrow + c * 64 + tid * 4);
        CP_COMMIT();
    };

#pragma unroll
    for (int i = 0; i < 8; i++) {
        int idx = tid + i * 128, row = idx >> 4, col = idx & 15;
        CP_ASYNC16(sb + row * RB + col * 16, Q + (size_t)row * ldq + col * 4);
    }
    CP_COMMIT();
    load_kv(0, 0);
    asm volatile("cp.async.wait_group 0;" ::: "memory");
    __syncthreads();

    const uint32_t* Qs = (const uint32_t*)smem;
    uint32_t qf[8][4];
    {
        int m0 = w * 16 + lr;
#pragma unroll
        for (int ds = 0; ds < 8; ds++) {
            qf[ds][0] = Qs[m0 * ST + ds * 8 + lc];
            qf[ds][1] = Qs[(m0 + 8) * ST + ds * 8 + lc];
            qf[ds][2] = Qs[m0 * ST + ds * 8 + lc + 4];
            qf[ds][3] = Qs[(m0 + 8) * ST + ds * 8 + lc + 4];
        }
    }

    float o[8][4];
#pragma unroll
    for (int dt = 0; dt < 8; dt++)
        o[dt][0] = o[dt][1] = o[dt][2] = o[dt][3] = 0.f;
    float m0r = -1e30f, m1r = -1e30f, l0 = 0.f, l1 = 0.f;

    for (int c = 0; c < 16; c++) {
        int buf = c & 1;
        asm volatile("cp.async.wait_group 0;" ::: "memory");
        __syncthreads();
        if (c + 1 < 16) load_kv(buf ^ 1, c + 1);

        const uint32_t* Ks = (const uint32_t*)(smem + KS + buf * TSZ);
        const uint32_t* Vs = (const uint32_t*)(smem + VS + buf * TSZ);
        const int* mk = (const int*)(smem + MK + buf * 256);

        float s[8][4];
#pragma unroll
        for (int j = 0; j < 8; j++) {
            s[j][0] = s[j][1] = s[j][2] = s[j][3] = 0.f;
#pragma unroll
            for (int ds = 0; ds < 8; ds++) {
                uint32_t bk[2];
                bk[0] = Ks[(j * 8 + lr) * ST + ds * 8 + lc];
                bk[1] = Ks[(j * 8 + lr) * ST + ds * 8 + lc + 4];
                mma8(s[j], qf[ds], bk);
            }
        }

        float mx0 = -1e30f, mx1 = -1e30f;
#pragma unroll
        for (int j = 0; j < 8; j++) {
            float ma0 = (mk[j * 8 + 2 * lc]     == 1) ? 0.f : -10000.f;
            float ma1 = (mk[j * 8 + 2 * lc + 1] == 1) ? 0.f : -10000.f;
            s[j][0] = s[j][0] * 0.125f + ma0;
            s[j][1] = s[j][1] * 0.125f + ma1;
            s[j][2] = s[j][2] * 0.125f + ma0;
            s[j][3] = s[j][3] * 0.125f + ma1;
            mx0 = fmaxf(mx0, fmaxf(s[j][0], s[j][1]));
            mx1 = fmaxf(mx1, fmaxf(s[j][2], s[j][3]));
        }
        mx0 = fmaxf(mx0, __shfl_xor_sync(0xffffffffu, mx0, 1));
        mx0 = fmaxf(mx0, __shfl_xor_sync(0xffffffffu, mx0, 2));
        mx1 = fmaxf(mx1, __shfl_xor_sync(0xffffffffu, mx1, 1));
        mx1 = fmaxf(mx1, __shfl_xor_sync(0xffffffffu, mx1, 2));

        float mn0 = fmaxf(m0r, mx0), mn1 = fmaxf(m1r, mx1);
        float al0 = __expf(m0r - mn0), al1 = __expf(m1r - mn1);
        m0r = mn0; m1r = mn1;

        float r0 = 0.f, r1 = 0.f;
#pragma unroll
        for (int j = 0; j < 8; j++) {
            s[j][0] = rnd_tf32(__expf(s[j][0] - m0r));
            s[j][1] = rnd_tf32(__expf(s[j][1] - m0r));
            s[j][2] = rnd_tf32(__expf(s[j][2] - m1r));
            s[j][3] = rnd_tf32(__expf(s[j][3] - m1r));
            r0 += s[j][0] + s[j][1];
            r1 += s[j][2] + s[j][3];
        }
        l0 = l0 * al0 + r0;
        l1 = l1 * al1 + r1;

#pragma unroll
        for (int dt = 0; dt < 8; dt++) {
            o[dt][0] *= al0; o[dt][1] *= al0;
            o[dt][2] *= al1; o[dt][3] *= al1;
        }

        int base = lane & ~3;
        int src0 = base + (lc >> 1), src1 = src0 + 2;
        bool odd = lc & 1;
#pragma unroll
        for (int kb = 0; kb < 8; kb++) {
            float v00 = __shfl_sync(0xffffffffu, s[kb][0], src0);
            float v01 = __shfl_sync(0xffffffffu, s[kb][1], src0);
            float v02 = __shfl_sync(0xffffffffu, s[kb][0], src1);
            float v03 = __shfl_sync(0xffffffffu, s[kb][1], src1);
            float v10 = __shfl_sync(0xffffffffu, s[kb][2], src0);
            float v11 = __shfl_sync(0xffffffffu, s[kb][3], src0);
            float v12 = __shfl_sync(0xffffffffu, s[kb][2], src1);
            float v13 = __shfl_sync(0xffffffffu, s[kb][3], src1);
            uint32_t aP[4];
            aP[0] = __float_as_uint(odd ? v01 : v00);
            aP[1] = __float_as_uint(odd ? v11 : v10);
            aP[2] = __float_as_uint(odd ? v03 : v02);
            aP[3] = __float_as_uint(odd ? v13 : v12);
#pragma unroll
            for (int dt = 0; dt < 8; dt++) {
                uint32_t bv[2];
                bv[0] = Vs[(kb * 8 + lc) * ST + dt * 8 + lr];
                bv[1] = Vs[(kb * 8 + lc + 4) * ST + dt * 8 + lr];
                mma8(o[dt], aP, bv);
            }
        }
    }

    l0 += __shfl_xor_sync(0xffffffffu, l0, 1);
    l0 += __shfl_xor_sync(0xffffffffu, l0, 2);
    l1 += __shfl_xor_sync(0xffffffffu, l1, 1);
    l1 += __shfl_xor_sync(0xffffffffu, l1, 2);
    float inv0 = 1.f / l0, inv1 = 1.f / l1;
    int row0 = w * 16 + lr, row1 = row0 + 8;
#pragma unroll
    for (int dt = 0; dt < 8; dt++) {
        int col = dt * 8 + 2 * lc;
        float2 v0 = make_float2(rnd_tf32(o[dt][0] * inv0), rnd_tf32(o[dt][1] * inv0));
        float2 v1 = make_float2(rnd_tf32(o[dt][2] * inv1), rnd_tf32(o[dt][3] * inv1));
        *(float2*)(O + (size_t)row0 * ldo + col) = v0;
        *(float2*)(O + (size_t)row1 * ldo + col) = v1;
    }
}

// ---------------------------------------------------------------------------
// tf32 mma.sync GEMM. C = A @ B^T (+bias/GELU/res/rnd)
// BM=BN=128, BK=32, 128 threads, 4 warps (2x2), warp tile 64x64.
// 2-stage cp.async, 2 CTA/SM. mode: bit0 = GELU, bit1 = round output.
// ---------------------------------------------------------------------------
__global__ void __launch_bounds__(128, 2)
mm_mma(const float* __restrict__ A, const float* __restrict__ B,
       const float* __restrict__ bias, const float* __restrict__ res,
       float* __restrict__ C, int K, int lda, int ldb, int ldc, int mode) {
    constexpr int BM = 128, BN = 128, BK = 32, AST = BK + 4;
    constexpr int ABYTES = BM * AST * 4;
    constexpr int BBYTES = BN * AST * 4;
    constexpr int MT = 4, NT = 8;          // 64x64 warp tile

    extern __shared__ char smem[];
    uint32_t sb = smem_u32(smem);
    uint32_t aoff[2] = { 0u, (uint32_t)(ABYTES + BBYTES) };
    uint32_t boff[2] = { (uint32_t)ABYTES, (uint32_t)(2 * ABYTES + BBYTES) };

    int tid = threadIdx.x;
    int wid = tid >> 5, lane = tid & 31;
    int warpM = wid >> 1, warpN = wid & 1;
    int lr = lane >> 2, lc = lane & 3;

    int rowBase = blockIdx.y * BM;
    int colBase = blockIdx.x * BN;

    float acc[MT][NT][4];
#pragma unroll
    for (int i = 0; i < MT; i++)
#pragma unroll
        for (int j = 0; j < NT; j++)
#pragma unroll
            for (int q = 0; q < 4; q++) acc[i][j][q] = 0.f;

    auto load_stage = [&](int buf, int k0) {
#pragma unroll
        for (int i = 0; i < (BM * 8) / 128; i++) {    // 8
            int idx = tid + i * 128;
            int row = idx >> 3, c = idx & 7;
            uint32_t dst = sb + aoff[buf] + (uint32_t)(row * (AST * 4) + c * 16);
            const float* src = A + (size_t)(rowBase + row) * lda + k0 + c * 4;
            CP_ASYNC16(dst, src);
        }
#pragma unroll
        for (int i = 0; i < (BN * 8) / 128; i++) {    // 8
            int idx = tid + i * 128;
            int row = idx >> 3, c = idx & 7;
            uint32_t dst = sb + boff[buf] + (uint32_t)(row * (AST * 4) + c * 16);
            const float* src = B + (size_t)(colBase + row) * ldb + k0 + c * 4;
            CP_ASYNC16(dst, src);
        }
        CP_COMMIT();
    };

    int nsteps = K / BK;
    load_stage(0, 0);
    load_stage(1, BK);

    for (int s = 0; s < nsteps; s++) {
        int buf = s & 1;
        if (s + 1 < nsteps) asm volatile("cp.async.wait_group 1;" ::: "memory");
        else                asm volatile("cp.async.wait_group 0;" ::: "memory");
        __syncthreads();

        const uint32_t* As = (const uint32_t*)(smem + aoff[buf]);
        const uint32_t* Bs = (const uint32_t*)(smem + boff[buf]);
#pragma unroll
        for (int kk = 0; kk < BK; kk += 8) {
            uint32_t af[MT][4], bf[NT][2];
#pragma unroll
            for (int i = 0; i < MT; i++) {
                int m0 = warpM * 64 + i * 16 + lr;
                int k = kk + lc;
                af[i][0] = As[m0 * AST + k];
                af[i][1] = As[(m0 + 8) * AST + k];
                af[i][2] = As[m0 * AST + k + 4];
                af[i][3] = As[(m0 + 8) * AST + k + 4];
            }
#pragma unroll
            for (int j = 0; j < NT; j++) {
                int n0 = warpN * 64 + j * 8 + lr;
                int k = kk + lc;
                bf[j][0] = Bs[n0 * AST + k];
                bf[j][1] = Bs[n0 * AST + k + 4];
            }
#pragma unroll
            for (int i = 0; i < MT; i++)
#pragma unroll
                for (int j = 0; j < NT; j++)
                    mma8(acc[i][j], af[i], bf[j]);
        }
        __syncthreads();
        if (s + 2 < nsteps) load_stage(buf, (s + 2) * BK);
    }

    bool gelu = mode & 1, rnd = mode & 2;
#pragma unroll
    for (int i = 0; i < MT; i++) {
#pragma unroll
        for (int j = 0; j < NT; j++) {
#pragma unroll
            for (int h = 0; h < 2; h++) {
                int r = rowBase + warpM * 64 + i * 16 + lr + h * 8;
                int cb = colBase + warpN * 64 + j * 8 + lc * 2;
                float v0 = acc[i][j][h * 2 + 0];
                float v1 = acc[i][j][h * 2 + 1];
                if (bias) { v0 += bias[cb]; v1 += bias[cb + 1]; }
                if (gelu) {
                    v0 = 0.5f * v0 * (1.f + erff(v0 * 0.70710678118654752f));
                    v1 = 0.5f * v1 * (1.f + erff(v1 * 0.70710678118654752f));
                }
                if (rnd) { v0 = rnd_tf32(v0); v1 = rnd_tf32(v1); }
                size_t off = (size_t)r * ldc + cb;
                if (res) {
                    float2 rv = *(const float2*)(res + off);
                    v0 += rv.x; v1 += rv.y;
                }
                *(float2*)(C + off) = make_float2(v0, v1);
            }
        }
    }
}

// ---------------------------------------------------------------------------
// Host-side launch orchestration
// ---------------------------------------------------------------------------
extern "C" void kernel_launch(void* const* d_in, const int* in_sizes, int n_in,
                              void* d_out, int out_size) {
    const float* x_in     = (const float*)d_in[0];
    const float* c_in     = (const float*)d_in[1];
    const int*   mask     = (const int*)d_in[2];
    const float* sa_qkv_w = (const float*)d_in[3];
    const float* sa_qkv_b = (const float*)d_in[4];
    const float* sa_proj_w= (const float*)d_in[5];
    const float* sa_proj_b= (const float*)d_in[6];
    const float* ca_q_w   = (const float*)d_in[7];
    const float* ca_q_b   = (const float*)d_in[8];
    const float* ca_k_w   = (const float*)d_in[9];
    const float* ca_k_b   = (const float*)d_in[10];
    const float* ca_v_w   = (const float*)d_in[11];
    const float* ca_v_b   = (const float*)d_in[12];
    const float* ca_proj_w= (const float*)d_in[13];
    const float* ca_proj_b= (const float*)d_in[14];
    const float* fc1_w    = (const float*)d_in[15];
    const float* fc1_b    = (const float*)d_in[16];
    const float* fc2_w    = (const float*)d_in[17];
    const float* fc2_b    = (const float*)d_in[18];

    float* xb = (float*)d_out;

    float *gh, *gqkv, *gattn, *gmlp, *gwt, *gbias;
    cudaGetSymbolAddress((void**)&gh,    g_h);
    cudaGetSymbolAddress((void**)&gqkv,  g_qkv);
    cudaGetSymbolAddress((void**)&gattn, g_attn);
    cudaGetSymbolAddress((void**)&gmlp,  g_mlp);
    cudaGetSymbolAddress((void**)&gwt,   g_wt);
    cudaGetSymbolAddress((void**)&gbias, g_bias);

    const int AST4 = (32 + 4) * 4;
    const int SMEM128 = 2 * (128 * AST4 + 128 * AST4);     // 73728
    const int SMEM_FLASH = 5 * (64 * 68 * 4) + 2 * 256;    // 87552
    cudaFuncSetAttribute(mm_mma, cudaFuncAttributeMaxDynamicSharedMemorySize, SMEM128);
    cudaFuncSetAttribute(flash_kernel, cudaFuncAttributeMaxDynamicSharedMemorySize, SMEM_FLASH);

    dim3 tblock(32, 8);
    dim3 fgrid(NSEQ / 64, HEADS, NBAT);

    // ---- batched weight transposes (one launch, start of graph) ----
    TArgs ta;
    const float* wins[8] = { sa_qkv_w, sa_proj_w, ca_q_w, ca_k_w,
                             ca_v_w, ca_proj_w, fc1_w, fc2_w };
    float* wouts[8] = { gwt + W_QKV, gwt + W_SAPROJ, gwt + W_CAQ, gwt + W_CAK,
                        gwt + W_CAV, gwt + W_CAPROJ, gwt + W_FC1, gwt + W_FC2 };
    int rows[8] = { 1024, 1024, 1024, 1024, 1024, 1024, 1024, 4096 };
    int cols[8] = { 3072, 1024, 1024, 1024, 1024, 1024, 4096, 1024 };
    int acc_t = 0;
    for (int i = 0; i < 8; i++) {
        ta.in[i] = wins[i]; ta.out[i] = wouts[i];
        ta.ldin[i] = cols[i]; ta.ldout[i] = rows[i];
        ta.tilesX[i] = cols[i] / 32;
        acc_t += (rows[i] / 32) * (cols[i] / 32);
        ta.tileEnd[i] = acc_t;
    }

    cudaMemcpyAsync(xb, x_in, (size_t)TOK * CDIM * sizeof(float),
                    cudaMemcpyDeviceToDevice, 0);
    cudaMemcpyAsync(gbias, ca_k_b, CDIM * sizeof(float), cudaMemcpyDeviceToDevice, 0);
    cudaMemcpyAsync(gbias + CDIM, ca_v_b, CDIM * sizeof(float), cudaMemcpyDeviceToDevice, 0);
    multi_transpose<<<acc_t, tblock>>>(ta);
    round_copy<<<TOK * CDIM / 4 / 256, 256>>>(c_in, gmlp);  // rounded c (gmlp free until MLP)

    // ===================== self-attention =====================
    ln_kernel<<<TOK, 256>>>(xb, gh);

    mm_mma<<<dim3(3072/128, TOK/128), 128, SMEM128>>>(
        gh, gwt + W_QKV, sa_qkv_b, nullptr, gqkv, 1024, 1024, 1024, 3072, 2);

    flash_kernel<<<fgrid, 128, SMEM_FLASH>>>(
        gqkv, gqkv + CDIM, gqkv + 2 * CDIM, mask, gattn, 3072, 3072, 1024,
        (long long)NSEQ * 3 * CDIM, (long long)NSEQ * 3 * CDIM,
        (long long)NSEQ * CDIM);

    mm_mma<<<dim3(CDIM/128, TOK/128), 128, SMEM128>>>(
        gattn, gwt + W_SAPROJ, sa_proj_b, xb, xb, 1024, 1024, 1024, 1024, 0);

    // ===================== cross-attention =====================
    ln_kernel<<<TOK, 256>>>(xb, gh);

    float* gq  = gqkv;
    float* gkv = gqkv + (size_t)TOK * CDIM;   // interleaved [TOK][2048]: k | v
    float* gcr = gmlp;

    mm_mma<<<dim3(CDIM/128, TOK/128), 128, SMEM128>>>(
        gh, gwt + W_CAQ, ca_q_b, nullptr, gq, 1024, 1024, 1024, 1024, 2);
    // fused K|V projection: B = [ca_k_w^T ; ca_v_w^T] contiguous, N=2048
    mm_mma<<<dim3(2048/128, TOK/128), 128, SMEM128>>>(
        gcr, gwt + W_CAK, gbias, nullptr, gkv, 1024, 1024, 1024, 2048, 2);

    flash_kernel<<<fgrid, 128, SMEM_FLASH>>>(
        gq, gkv, gkv + CDIM, mask, gattn, 1024, 2048, 1024,
        (long long)NSEQ * CDIM, (long long)NSEQ * 2048,
        (long long)NSEQ * CDIM);

    mm_mma<<<dim3(CDIM/128, TOK/128), 128, SMEM128>>>(
        gattn, gwt + W_CAPROJ, ca_proj_b, xb, xb, 1024, 1024, 1024, 1024, 0);

    // ===================== MLP =====================
    ln_kernel<<<TOK, 256>>>(xb, gh);

    mm_mma<<<dim3(4096/128, TOK/128), 128, SMEM128>>>(
        gh, gwt + W_FC1, fc1_b, nullptr, gmlp, 1024, 1024, 1024, 4096, 3);

    mm_mma<<<dim3(CDIM/128, TOK/128), 128, SMEM128>>>(
        gmlp, gwt + W_FC2, fc2_b, xb, xb, 4096, 4096, 4096, 1024, 0);
}

// round 11
// speedup vs baseline: 2.4237x; 1.7613x over previous
#include <cuda_runtime.h>
#include <cuda_fp16.h>
#include <math.h>
#include <stdint.h>

// Problem constants
#define TOK   4096         // B*N
#define CDIM  1024
#define HEADS 16
#define NBAT  4
#define NSEQ  1024
#define HD    64

// Scratch (device globals: allocation-free per harness rules)
__device__ __align__(256) __half g_h[TOK * CDIM];                 // 8 MB  LN out
__device__ __align__(256) __half g_qkv[TOK * 3 * CDIM];           // 24 MB q / interleaved kv
__device__ __align__(256) __half g_attn[TOK * CDIM];              // 8 MB
__device__ __align__(256) __half g_mlp[TOK * 4 * CDIM];           // 32 MB (also rounded-c)
__device__ __align__(256) __half g_wt[16777216];                  // 32 MB transposed weights
__device__ __align__(256) float  g_bias[2048];                    // ca_k_b || ca_v_b

// g_wt half-element offsets
#define W_QKV    0
#define W_SAPROJ 3145728
#define W_CAQ    4194304
#define W_CAK    5242880
#define W_CAV    6291456
#define W_CAPROJ 7340032
#define W_FC1    8388608
#define W_FC2    12582912

// ---------------------------------------------------------------------------
// Helpers
// ---------------------------------------------------------------------------
__device__ __forceinline__ uint32_t smem_u32(const void* p) {
    uint32_t a;
    asm("{ .reg .u64 t; cvta.to.shared.u64 t, %1; cvt.u32.u64 %0, t; }" : "=r"(a) : "l"(p));
    return a;
}
// pack(lo, hi) -> f16x2
__device__ __forceinline__ uint32_t pkh(float lo, float hi) {
    uint32_t r;
    asm("cvt.rn.f16x2.f32 %0, %1, %2;" : "=r"(r) : "f"(hi), "f"(lo));
    return r;
}
#define CP_ASYNC16(dst, src) \
    asm volatile("cp.async.cg.shared.global [%0], [%1], 16;" :: "r"(dst), "l"(src) : "memory")
#define CP_COMMIT()  asm volatile("cp.async.commit_group;" ::: "memory")

__device__ __forceinline__ void mma16(float* d, const uint32_t* a, const uint32_t* b) {
    asm volatile("mma.sync.aligned.m16n8k16.row.col.f32.f16.f16.f32 "
                 "{%0,%1,%2,%3}, {%4,%5,%6,%7}, {%8,%9}, {%0,%1,%2,%3};"
                 : "+f"(d[0]), "+f"(d[1]), "+f"(d[2]), "+f"(d[3])
                 : "r"(a[0]), "r"(a[1]), "r"(a[2]), "r"(a[3]), "r"(b[0]), "r"(b[1]));
}

// ---------------------------------------------------------------------------
// LayerNorm (no affine, eps=1e-6): f32 in, f16 out (feeds MMA only)
// ---------------------------------------------------------------------------
__global__ void ln_kernel(const float* __restrict__ in, __half* __restrict__ out) {
    __shared__ float sred[256];
    int row = blockIdx.x;
    const float4* p = (const float4*)(in + (size_t)row * CDIM);
    float4 v = p[threadIdx.x];
    float s = v.x + v.y + v.z + v.w;
    sred[threadIdx.x] = s; __syncthreads();
    for (int o = 128; o > 0; o >>= 1) {
        if (threadIdx.x < o) sred[threadIdx.x] += sred[threadIdx.x + o];
        __syncthreads();
    }
    float mean = sred[0] * (1.f / CDIM);
    __syncthreads();
    float dx = v.x-mean, dy = v.y-mean, dz = v.z-mean, dw = v.w-mean;
    sred[threadIdx.x] = dx*dx + dy*dy + dz*dz + dw*dw; __syncthreads();
    for (int o = 128; o > 0; o >>= 1) {
        if (threadIdx.x < o) sred[threadIdx.x] += sred[threadIdx.x + o];
        __syncthreads();
    }
    float inv = rsqrtf(sred[0] * (1.f / CDIM) + 1e-6f);
    uint2 r;
    r.x = pkh(dx * inv, dy * inv);
    r.y = pkh(dz * inv, dw * inv);
    ((uint2*)(out + (size_t)row * CDIM))[threadIdx.x] = r;
}

// ---------------------------------------------------------------------------
// f32 -> f16 copy (for raw c input feeding K/V GEMMs)
// ---------------------------------------------------------------------------
__global__ void half_copy(const float* __restrict__ in, __half* __restrict__ out) {
    size_t i = (size_t)blockIdx.x * 256 + threadIdx.x;
    float4 v = ((const float4*)in)[i];
    uint2 r;
    r.x = pkh(v.x, v.y);
    r.y = pkh(v.z, v.w);
    ((uint2*)out)[i] = r;
}

// ---------------------------------------------------------------------------
// Batched multi-weight 32x32 tiled transpose -> f16 (one launch)
// ---------------------------------------------------------------------------
struct TArgs {
    const float* in[8];
    __half* out[8];
    int ldin[8];
    int ldout[8];
    int tilesX[8];
    int tileEnd[8];
};

__global__ void multi_transpose(TArgs a) {
    __shared__ float t[32][33];
    int bid = blockIdx.x;
    int s = 0;
#pragma unroll
    for (int i = 0; i < 8; i++)
        if (bid >= a.tileEnd[i]) s = i + 1;
    int t0 = s ? a.tileEnd[s - 1] : 0;
    int lt = bid - t0;
    int tx = lt % a.tilesX[s], ty = lt / a.tilesX[s];
    const float* in = a.in[s];
    __half* out = a.out[s];
    int ldin = a.ldin[s], ldout = a.ldout[s];
    int c0 = tx * 32, r0 = ty * 32;
    int x = threadIdx.x, y = threadIdx.y;
#pragma unroll
    for (int i = 0; i < 32; i += 8)
        t[y + i][x] = in[(size_t)(r0 + y + i) * ldin + c0 + x];
    __syncthreads();
#pragma unroll
    for (int i = 0; i < 32; i += 8)
        out[(size_t)(c0 + y + i) * ldout + r0 + x] = __float2half_rn(t[x][y + i]);
}

// ---------------------------------------------------------------------------
// Fused flash-attention (fp16 mma.sync), non-causal, additive key mask.
//   Per CTA: 64 query rows of one (batch, head). 128 threads, 4 warps.
//   f32 accumulate + online softmax; P stays in registers (C-frag == A-frag
//   for fp16); V fed via ldmatrix.x4.trans. Output f16.
// ---------------------------------------------------------------------------
__global__ void __launch_bounds__(128, 2)
flash_kernel(const __half* __restrict__ Qp, const __half* __restrict__ Kp,
             const __half* __restrict__ Vp, const int* __restrict__ mask,
             __half* __restrict__ Op, int ldq, int ldkv, int ldo,
             long long sQb, long long sKb, long long sOb) {
    constexpr int STH = 72;          // halves per smem row (64 + 8 pad)
    constexpr int ST32 = STH / 2;    // 36 u32 per row
    constexpr int RB  = STH * 2;     // 144 bytes
    constexpr int TSZ = 64 * RB;     // 9216 bytes per tile
    const int KS = TSZ;              // K bufs at TSZ, 2*TSZ
    const int VS = TSZ * 3;          // V bufs at 3*TSZ, 4*TSZ
    const int MK = TSZ * 5;          // mask bufs 256B each

    extern __shared__ char smem[];
    uint32_t sb = smem_u32(smem);

    int tid = threadIdx.x, w = tid >> 5, lane = tid & 31;
    int lr = lane >> 2, lc = lane & 3;
    int qt = blockIdx.x, h = blockIdx.y, bz = blockIdx.z;

    const __half* Q = Qp + bz * sQb + (size_t)h * HD + (size_t)qt * 64 * ldq;
    const __half* K = Kp + bz * sKb + (size_t)h * HD;
    const __half* V = Vp + bz * sKb + (size_t)h * HD;
    const int* mrow = mask + bz * NSEQ;
    __half* O = Op + bz * sOb + (size_t)h * HD + (size_t)qt * 64 * ldo;

    auto load_kv = [&](int buf, int c) {
#pragma unroll
        for (int i = 0; i < 4; i++) {
            int idx = tid + i * 128, row = idx >> 3, col = idx & 7;
            CP_ASYNC16(sb + KS + buf * TSZ + row * RB + col * 16,
                       K + (size_t)(c * 64 + row) * ldkv + col * 8);
        }
#pragma unroll
        for (int i = 0; i < 4; i++) {
            int idx = tid + i * 128, row = idx >> 3, col = idx & 7;
            CP_ASYNC16(sb + VS + buf * TSZ + row * RB + col * 16,
                       V + (size_t)(c * 64 + row) * ldkv + col * 8);
        }
        if (tid < 16)
            CP_ASYNC16(sb + MK + buf * 256 + tid * 16, mrow + c * 64 + tid * 4);
        CP_COMMIT();
    };

    // Q tile + first K/V chunk
#pragma unroll
    for (int i = 0; i < 4; i++) {
        int idx = tid + i * 128, row = idx >> 3, col = idx & 7;
        CP_ASYNC16(sb + row * RB + col * 16, Q + (size_t)row * ldq + col * 8);
    }
    CP_COMMIT();
    load_kv(0, 0);
    asm volatile("cp.async.wait_group 0;" ::: "memory");
    __syncthreads();

    // Preload Q fragments (A-frag m16n8k16) for 4 d-chunks of 16
    const uint32_t* Qs = (const uint32_t*)smem;
    uint32_t qf[4][4];
    {
        int m0 = w * 16 + lr;
#pragma unroll
        for (int ds = 0; ds < 4; ds++) {
            qf[ds][0] = Qs[m0 * ST32 + ds * 8 + lc];
            qf[ds][1] = Qs[(m0 + 8) * ST32 + ds * 8 + lc];
            qf[ds][2] = Qs[m0 * ST32 + ds * 8 + 4 + lc];
            qf[ds][3] = Qs[(m0 + 8) * ST32 + ds * 8 + 4 + lc];
        }
    }

    float o[8][4];
#pragma unroll
    for (int dt = 0; dt < 8; dt++)
        o[dt][0] = o[dt][1] = o[dt][2] = o[dt][3] = 0.f;
    float m0r = -1e30f, m1r = -1e30f, l0 = 0.f, l1 = 0.f;

    for (int c = 0; c < 16; c++) {
        int buf = c & 1;
        asm volatile("cp.async.wait_group 0;" ::: "memory");
        __syncthreads();
        if (c + 1 < 16) load_kv(buf ^ 1, c + 1);

        const uint32_t* Ks = (const uint32_t*)(smem + KS + buf * TSZ);
        uint32_t vbase = sb + VS + buf * TSZ;
        const int* mk = (const int*)(smem + MK + buf * 256);

        // S = Q @ K^T (8 n-tiles of 8 keys, 4 k16 steps over d)
        float s[8][4];
#pragma unroll
        for (int j = 0; j < 8; j++) {
            s[j][0] = s[j][1] = s[j][2] = s[j][3] = 0.f;
#pragma unroll
            for (int ds = 0; ds < 4; ds++) {
                uint32_t bk[2];
                bk[0] = Ks[(j * 8 + lr) * ST32 + ds * 8 + lc];
                bk[1] = Ks[(j * 8 + lr) * ST32 + ds * 8 + 4 + lc];
                mma16(s[j], qf[ds], bk);
            }
        }

        // scale + mask, chunk row max
        float mx0 = -1e30f, mx1 = -1e30f;
#pragma unroll
        for (int j = 0; j < 8; j++) {
            float ma0 = (mk[j * 8 + 2 * lc]     == 1) ? 0.f : -10000.f;
            float ma1 = (mk[j * 8 + 2 * lc + 1] == 1) ? 0.f : -10000.f;
            s[j][0] = s[j][0] * 0.125f + ma0;
            s[j][1] = s[j][1] * 0.125f + ma1;
            s[j][2] = s[j][2] * 0.125f + ma0;
            s[j][3] = s[j][3] * 0.125f + ma1;
            mx0 = fmaxf(mx0, fmaxf(s[j][0], s[j][1]));
            mx1 = fmaxf(mx1, fmaxf(s[j][2], s[j][3]));
        }
        mx0 = fmaxf(mx0, __shfl_xor_sync(0xffffffffu, mx0, 1));
        mx0 = fmaxf(mx0, __shfl_xor_sync(0xffffffffu, mx0, 2));
        mx1 = fmaxf(mx1, __shfl_xor_sync(0xffffffffu, mx1, 1));
        mx1 = fmaxf(mx1, __shfl_xor_sync(0xffffffffu, mx1, 2));

        float mn0 = fmaxf(m0r, mx0), mn1 = fmaxf(m1r, mx1);
        float al0 = __expf(m0r - mn0), al1 = __expf(m1r - mn1);
        m0r = mn0; m1r = mn1;

        float r0 = 0.f, r1 = 0.f;
#pragma unroll
        for (int j = 0; j < 8; j++) {
            s[j][0] = __expf(s[j][0] - m0r);
            s[j][1] = __expf(s[j][1] - m0r);
            s[j][2] = __expf(s[j][2] - m1r);
            s[j][3] = __expf(s[j][3] - m1r);
            r0 += s[j][0] + s[j][1];
            r1 += s[j][2] + s[j][3];
        }
        l0 = l0 * al0 + r0;
        l1 = l1 * al1 + r1;

#pragma unroll
        for (int dt = 0; dt < 8; dt++) {
            o[dt][0] *= al0; o[dt][1] *= al0;
            o[dt][2] *= al1; o[dt][3] *= al1;
        }

        // O += P @ V : fp16 C-frag == A-frag (pack only); V via ldmatrix.trans
        int m = lane >> 3, rIn = lane & 7;
#pragma unroll
        for (int kb = 0; kb < 4; kb++) {
            uint32_t aP[4];
            aP[0] = pkh(s[2*kb][0],   s[2*kb][1]);
            aP[1] = pkh(s[2*kb][2],   s[2*kb][3]);
            aP[2] = pkh(s[2*kb+1][0], s[2*kb+1][1]);
            aP[3] = pkh(s[2*kb+1][2], s[2*kb+1][3]);
            int key = kb * 16 + ((m & 1) ? 8 : 0) + rIn;
#pragma unroll
            for (int dtp = 0; dtp < 4; dtp++) {
                int dcol = (2 * dtp + (m >> 1)) * 8;
                uint32_t addr = vbase + (uint32_t)(key * RB + dcol * 2);
                uint32_t bv[4];
                asm volatile("ldmatrix.sync.aligned.m8n8.x4.trans.shared.b16 "
                             "{%0,%1,%2,%3}, [%4];"
                             : "=r"(bv[0]), "=r"(bv[1]), "=r"(bv[2]), "=r"(bv[3])
                             : "r"(addr));
                mma16(o[2*dtp],     aP, bv);
                mma16(o[2*dtp + 1], aP, bv + 2);
            }
        }
    }

    // finalize: row sums across quad, normalize, convert, store f16
    l0 += __shfl_xor_sync(0xffffffffu, l0, 1);
    l0 += __shfl_xor_sync(0xffffffffu, l0, 2);
    l1 += __shfl_xor_sync(0xffffffffu, l1, 1);
    l1 += __shfl_xor_sync(0xffffffffu, l1, 2);
    float inv0 = 1.f / l0, inv1 = 1.f / l1;
    int row0 = w * 16 + lr, row1 = row0 + 8;
#pragma unroll
    for (int dt = 0; dt < 8; dt++) {
        int col = dt * 8 + 2 * lc;
        *(uint32_t*)(O + (size_t)row0 * ldo + col) = pkh(o[dt][0] * inv0, o[dt][1] * inv0);
        *(uint32_t*)(O + (size_t)row1 * ldo + col) = pkh(o[dt][2] * inv1, o[dt][3] * inv1);
    }
}

// ---------------------------------------------------------------------------
// fp16 mma.sync GEMM. C = A @ B^T (+bias f32)(+GELU)(res f32 / out f16 or f32)
// BM=BN=128, BK=32, 128 threads, 4 warps (2x2), warp tile 64x64.
// 3-stage cp.async, ONE __syncthreads per stage, 2 CTA/SM.
// mode: bit0 = GELU, bit1 = output f16 (else f32 with optional res add).
// ---------------------------------------------------------------------------
__global__ void __launch_bounds__(128, 2)
mm_h(const __half* __restrict__ A, const __half* __restrict__ B,
     const float* __restrict__ bias, const float* __restrict__ res,
     void* __restrict__ Cout, int K, int lda, int ldb, int ldc, int mode) {
    constexpr int BM = 128, BN = 128, BK = 32;
    constexpr int STH = BK + 8;            // 40 halves per row
    constexpr int ST32 = STH / 2;          // 20 u32
    constexpr int RB = STH * 2;            // 80 bytes
    constexpr int OPB = BM * RB;           // 10240 bytes per operand stage
    constexpr int STG = 2 * OPB;           // 20480 per stage (A+B)
    constexpr int MT = 4, NT = 8;

    extern __shared__ char smem[];
    uint32_t sb = smem_u32(smem);

    int tid = threadIdx.x;
    int wid = tid >> 5, lane = tid & 31;
    int warpM = wid >> 1, warpN = wid & 1;
    int lr = lane >> 2, lc = lane & 3;

    int rowBase = blockIdx.y * BM;
    int colBase = blockIdx.x * BN;

    float acc[MT][NT][4];
#pragma unroll
    for (int i = 0; i < MT; i++)
#pragma unroll
        for (int j = 0; j < NT; j++)
#pragma unroll
            for (int q = 0; q < 4; q++) acc[i][j][q] = 0.f;

    auto load_stage = [&](int buf, int k0) {
#pragma unroll
        for (int i = 0; i < 4; i++) {                   // A: 128 rows x 4 chunks
            int idx = tid + i * 128;
            int row = idx >> 2, c = idx & 3;
            CP_ASYNC16(sb + buf * STG + (uint32_t)(row * RB + c * 16),
                       A + (size_t)(rowBase + row) * lda + k0 + c * 8);
        }
#pragma unroll
        for (int i = 0; i < 4; i++) {                   // B
            int idx = tid + i * 128;
            int row = idx >> 2, c = idx & 3;
            CP_ASYNC16(sb + buf * STG + OPB + (uint32_t)(row * RB + c * 16),
                       B + (size_t)(colBase + row) * ldb + k0 + c * 8);
        }
        CP_COMMIT();
    };

    int nsteps = K / BK;
    load_stage(0, 0);
    load_stage(1, BK);

    for (int s = 0; s < nsteps; s++) {
        int buf = s % 3;
        if (s + 1 < nsteps) asm volatile("cp.async.wait_group 1;" ::: "memory");
        else                asm volatile("cp.async.wait_group 0;" ::: "memory");
        __syncthreads();
        if (s + 2 < nsteps) load_stage((s + 2) % 3, (s + 2) * BK);

        const uint32_t* As = (const uint32_t*)(smem + buf * STG);
        const uint32_t* Bs = (const uint32_t*)(smem + buf * STG + OPB);
#pragma unroll
        for (int kk2 = 0; kk2 < 2; kk2++) {             // two k16 steps
            int kc = kk2 * 8;
            uint32_t af[MT][4], bf[NT][2];
#pragma unroll
            for (int i = 0; i < MT; i++) {
                int m0 = warpM * 64 + i * 16 + lr;
                af[i][0] = As[m0 * ST32 + kc + lc];
                af[i][1] = As[(m0 + 8) * ST32 + kc + lc];
                af[i][2] = As[m0 * ST32 + kc + 4 + lc];
                af[i][3] = As[(m0 + 8) * ST32 + kc + 4 + lc];
            }
#pragma unroll
            for (int j = 0; j < NT; j++) {
                int n0 = warpN * 64 + j * 8 + lr;
                bf[j][0] = Bs[n0 * ST32 + kc + lc];
                bf[j][1] = Bs[n0 * ST32 + kc + 4 + lc];
            }
#pragma unroll
            for (int i = 0; i < MT; i++)
#pragma unroll
                for (int j = 0; j < NT; j++)
                    mma16(acc[i][j], af[i], bf[j]);
        }
    }
    __syncthreads();

    bool gelu = mode & 1, outh = mode & 2;
#pragma unroll
    for (int i = 0; i < MT; i++) {
#pragma unroll
        for (int j = 0; j < NT; j++) {
#pragma unroll
            for (int h = 0; h < 2; h++) {
                int r = rowBase + warpM * 64 + i * 16 + lr + h * 8;
                int cb = colBase + warpN * 64 + j * 8 + lc * 2;
                float v0 = acc[i][j][h * 2 + 0];
                float v1 = acc[i][j][h * 2 + 1];
                if (bias) { v0 += bias[cb]; v1 += bias[cb + 1]; }
                if (gelu) {
                    v0 = 0.5f * v0 * (1.f + erff(v0 * 0.70710678118654752f));
                    v1 = 0.5f * v1 * (1.f + erff(v1 * 0.70710678118654752f));
                }
                size_t off = (size_t)r * ldc + cb;
                if (outh) {
                    *(uint32_t*)((__half*)Cout + off) = pkh(v0, v1);
                } else {
                    if (res) {
                        float2 rv = *(const float2*)(res + off);
                        v0 += rv.x; v1 += rv.y;
                    }
                    *(float2*)((float*)Cout + off) = make_float2(v0, v1);
                }
            }
        }
    }
}

// ---------------------------------------------------------------------------
// Host-side launch orchestration
// ---------------------------------------------------------------------------
extern "C" void kernel_launch(void* const* d_in, const int* in_sizes, int n_in,
                              void* d_out, int out_size) {
    const float* x_in     = (const float*)d_in[0];
    const float* c_in     = (const float*)d_in[1];
    const int*   mask     = (const int*)d_in[2];
    const float* sa_qkv_w = (const float*)d_in[3];
    const float* sa_qkv_b = (const float*)d_in[4];
    const float* sa_proj_w= (const float*)d_in[5];
    const float* sa_proj_b= (const float*)d_in[6];
    const float* ca_q_w   = (const float*)d_in[7];
    const float* ca_q_b   = (const float*)d_in[8];
    const float* ca_k_w   = (const float*)d_in[9];
    const float* ca_k_b   = (const float*)d_in[10];
    const float* ca_v_w   = (const float*)d_in[11];
    const float* ca_v_b   = (const float*)d_in[12];
    const float* ca_proj_w= (const float*)d_in[13];
    const float* ca_proj_b= (const float*)d_in[14];
    const float* fc1_w    = (const float*)d_in[15];
    const float* fc1_b    = (const float*)d_in[16];
    const float* fc2_w    = (const float*)d_in[17];
    const float* fc2_b    = (const float*)d_in[18];

    float* xb = (float*)d_out;

    __half *gh, *gqkv, *gattn, *gmlp, *gwt;
    float *gbias;
    cudaGetSymbolAddress((void**)&gh,    g_h);
    cudaGetSymbolAddress((void**)&gqkv,  g_qkv);
    cudaGetSymbolAddress((void**)&gattn, g_attn);
    cudaGetSymbolAddress((void**)&gmlp,  g_mlp);
    cudaGetSymbolAddress((void**)&gwt,   g_wt);
    cudaGetSymbolAddress((void**)&gbias, g_bias);

    const int SMEM_MM = 3 * 2 * 128 * 80;                 // 61440
    const int SMEM_FLASH = 5 * (64 * 144) + 2 * 256;      // 46592
    cudaFuncSetAttribute(mm_h, cudaFuncAttributeMaxDynamicSharedMemorySize, SMEM_MM);
    cudaFuncSetAttribute(flash_kernel, cudaFuncAttributeMaxDynamicSharedMemorySize, SMEM_FLASH);

    dim3 tblock(32, 8);
    dim3 fgrid(NSEQ / 64, HEADS, NBAT);

    // ---- batched weight transposes (one launch) ----
    TArgs ta;
    const float* wins[8] = { sa_qkv_w, sa_proj_w, ca_q_w, ca_k_w,
                             ca_v_w, ca_proj_w, fc1_w, fc2_w };
    __half* wouts[8] = { gwt + W_QKV, gwt + W_SAPROJ, gwt + W_CAQ, gwt + W_CAK,
                         gwt + W_CAV, gwt + W_CAPROJ, gwt + W_FC1, gwt + W_FC2 };
    int rows[8] = { 1024, 1024, 1024, 1024, 1024, 1024, 1024, 4096 };
    int cols[8] = { 3072, 1024, 1024, 1024, 1024, 1024, 4096, 1024 };
    int acc_t = 0;
    for (int i = 0; i < 8; i++) {
        ta.in[i] = wins[i]; ta.out[i] = wouts[i];
        ta.ldin[i] = cols[i]; ta.ldout[i] = rows[i];
        ta.tilesX[i] = cols[i] / 32;
        acc_t += (rows[i] / 32) * (cols[i] / 32);
        ta.tileEnd[i] = acc_t;
    }

    cudaMemcpyAsync(xb, x_in, (size_t)TOK * CDIM * sizeof(float),
                    cudaMemcpyDeviceToDevice, 0);
    cudaMemcpyAsync(gbias, ca_k_b, CDIM * sizeof(float), cudaMemcpyDeviceToDevice, 0);
    cudaMemcpyAsync(gbias + CDIM, ca_v_b, CDIM * sizeof(float), cudaMemcpyDeviceToDevice, 0);
    multi_transpose<<<acc_t, tblock>>>(ta);
    half_copy<<<TOK * CDIM / 4 / 256, 256>>>(c_in, gmlp);   // f16 copy of c

    // ===================== self-attention =====================
    ln_kernel<<<TOK, 256>>>(xb, gh);

    mm_h<<<dim3(3072/128, TOK/128), 128, SMEM_MM>>>(
        gh, gwt + W_QKV, sa_qkv_b, nullptr, gqkv, 1024, 1024, 1024, 3072, 2);

    flash_kernel<<<fgrid, 128, SMEM_FLASH>>>(
        gqkv, gqkv + CDIM, gqkv + 2 * CDIM, mask, gattn, 3072, 3072, 1024,
        (long long)NSEQ * 3 * CDIM, (long long)NSEQ * 3 * CDIM,
        (long long)NSEQ * CDIM);

    mm_h<<<dim3(CDIM/128, TOK/128), 128, SMEM_MM>>>(
        gattn, gwt + W_SAPROJ, sa_proj_b, xb, xb, 1024, 1024, 1024, 1024, 0);

    // ===================== cross-attention =====================
    ln_kernel<<<TOK, 256>>>(xb, gh);

    __half* gq  = gqkv;
    __half* gkv = gqkv + (size_t)TOK * CDIM;   // interleaved [TOK][2048]: k | v
    __half* gcr = gmlp;

    mm_h<<<dim3(CDIM/128, TOK/128), 128, SMEM_MM>>>(
        gh, gwt + W_CAQ, ca_q_b, nullptr, gq, 1024, 1024, 1024, 1024, 2);
    // fused K|V projection: B = [ca_k_w^T ; ca_v_w^T] contiguous, N=2048
    mm_h<<<dim3(2048/128, TOK/128), 128, SMEM_MM>>>(
        gcr, gwt + W_CAK, gbias, nullptr, gkv, 1024, 1024, 1024, 2048, 2);

    flash_kernel<<<fgrid, 128, SMEM_FLASH>>>(
        gq, gkv, gkv + CDIM, mask, gattn, 1024, 2048, 1024,
        (long long)NSEQ * CDIM, (long long)NSEQ * 2048,
        (long long)NSEQ * CDIM);

    mm_h<<<dim3(CDIM/128, TOK/128), 128, SMEM_MM>>>(
        gattn, gwt + W_CAPROJ, ca_proj_b, xb, xb, 1024, 1024, 1024, 1024, 0);

    // ===================== MLP =====================
    ln_kernel<<<TOK, 256>>>(xb, gh);

    mm_h<<<dim3(4096/128, TOK/128), 128, SMEM_MM>>>(
        gh, gwt + W_FC1, fc1_b, nullptr, gmlp, 1024, 1024, 1024, 4096, 3);

    mm_h<<<dim3(CDIM/128, TOK/128), 128, SMEM_MM>>>(
        gmlp, gwt + W_FC2, fc2_b, xb, xb, 4096, 4096, 4096, 1024, 0);
}

// round 12
// speedup vs baseline: 2.6063x; 1.0753x over previous
#include <cuda_runtime.h>
#include <cuda_fp16.h>
#include <math.h>
#include <stdint.h>

// Problem constants
#define TOK   4096         // B*N
#define CDIM  1024
#define HEADS 16
#define NBAT  4
#define NSEQ  1024
#define HD    64

// Scratch (device globals: allocation-free per harness rules)
__device__ __align__(256) __half g_h[TOK * CDIM];                 // 8 MB  LN out
__device__ __align__(256) __half g_qkv[TOK * 3 * CDIM];           // 24 MB q / interleaved kv
__device__ __align__(256) __half g_attn[TOK * CDIM];              // 8 MB
__device__ __align__(256) __half g_mlp[TOK * 4 * CDIM];           // 32 MB (also f16 c)
__device__ __align__(256) __half g_wt[16777216];                  // 32 MB transposed weights
__device__ __align__(256) float  g_bias[2048];                    // ca_k_b || ca_v_b

// g_wt half-element offsets
#define W_QKV    0
#define W_SAPROJ 3145728
#define W_CAQ    4194304
#define W_CAK    5242880
#define W_CAV    6291456
#define W_CAPROJ 7340032
#define W_FC1    8388608
#define W_FC2    12582912

// ---------------------------------------------------------------------------
// Helpers
// ---------------------------------------------------------------------------
__device__ __forceinline__ uint32_t smem_u32(const void* p) {
    uint32_t a;
    asm("{ .reg .u64 t; cvta.to.shared.u64 t, %1; cvt.u32.u64 %0, t; }" : "=r"(a) : "l"(p));
    return a;
}
// pack(lo, hi) -> f16x2
__device__ __forceinline__ uint32_t pkh(float lo, float hi) {
    uint32_t r;
    asm("cvt.rn.f16x2.f32 %0, %1, %2;" : "=r"(r) : "f"(hi), "f"(lo));
    return r;
}
#define CP_ASYNC16(dst, src) \
    asm volatile("cp.async.cg.shared.global [%0], [%1], 16;" :: "r"(dst), "l"(src) : "memory")
#define CP_COMMIT()  asm volatile("cp.async.commit_group;" ::: "memory")

__device__ __forceinline__ void mma16(float* d, const uint32_t* a, const uint32_t* b) {
    asm volatile("mma.sync.aligned.m16n8k16.row.col.f32.f16.f16.f32 "
                 "{%0,%1,%2,%3}, {%4,%5,%6,%7}, {%8,%9}, {%0,%1,%2,%3};"
                 : "+f"(d[0]), "+f"(d[1]), "+f"(d[2]), "+f"(d[3])
                 : "r"(a[0]), "r"(a[1]), "r"(a[2]), "r"(a[3]), "r"(b[0]), "r"(b[1]));
}
#define LDM_X4(r0, r1, r2, r3, addr) \
    asm volatile("ldmatrix.sync.aligned.m8n8.x4.shared.b16 {%0,%1,%2,%3}, [%4];" \
                 : "=r"(r0), "=r"(r1), "=r"(r2), "=r"(r3) : "r"(addr))

// ---------------------------------------------------------------------------
// LayerNorm (no affine, eps=1e-6): f32 in, f16 out (feeds MMA only)
// ---------------------------------------------------------------------------
__global__ void ln_kernel(const float* __restrict__ in, __half* __restrict__ out) {
    __shared__ float sred[256];
    int row = blockIdx.x;
    const float4* p = (const float4*)(in + (size_t)row * CDIM);
    float4 v = p[threadIdx.x];
    float s = v.x + v.y + v.z + v.w;
    sred[threadIdx.x] = s; __syncthreads();
    for (int o = 128; o > 0; o >>= 1) {
        if (threadIdx.x < o) sred[threadIdx.x] += sred[threadIdx.x + o];
        __syncthreads();
    }
    float mean = sred[0] * (1.f / CDIM);
    __syncthreads();
    float dx = v.x-mean, dy = v.y-mean, dz = v.z-mean, dw = v.w-mean;
    sred[threadIdx.x] = dx*dx + dy*dy + dz*dz + dw*dw; __syncthreads();
    for (int o = 128; o > 0; o >>= 1) {
        if (threadIdx.x < o) sred[threadIdx.x] += sred[threadIdx.x + o];
        __syncthreads();
    }
    float inv = rsqrtf(sred[0] * (1.f / CDIM) + 1e-6f);
    uint2 r;
    r.x = pkh(dx * inv, dy * inv);
    r.y = pkh(dz * inv, dw * inv);
    ((uint2*)(out + (size_t)row * CDIM))[threadIdx.x] = r;
}

// ---------------------------------------------------------------------------
// f32 -> f16 copy (for raw c input feeding K/V GEMMs)
// ---------------------------------------------------------------------------
__global__ void half_copy(const float* __restrict__ in, __half* __restrict__ out) {
    size_t i = (size_t)blockIdx.x * 256 + threadIdx.x;
    float4 v = ((const float4*)in)[i];
    uint2 r;
    r.x = pkh(v.x, v.y);
    r.y = pkh(v.z, v.w);
    ((uint2*)out)[i] = r;
}

// ---------------------------------------------------------------------------
// Batched multi-weight 32x32 tiled transpose -> f16 (one launch)
// ---------------------------------------------------------------------------
struct TArgs {
    const float* in[8];
    __half* out[8];
    int ldin[8];
    int ldout[8];
    int tilesX[8];
    int tileEnd[8];
};

__global__ void multi_transpose(TArgs a) {
    __shared__ float t[32][33];
    int bid = blockIdx.x;
    int s = 0;
#pragma unroll
    for (int i = 0; i < 8; i++)
        if (bid >= a.tileEnd[i]) s = i + 1;
    int t0 = s ? a.tileEnd[s - 1] : 0;
    int lt = bid - t0;
    int tx = lt % a.tilesX[s], ty = lt / a.tilesX[s];
    const float* in = a.in[s];
    __half* out = a.out[s];
    int ldin = a.ldin[s], ldout = a.ldout[s];
    int c0 = tx * 32, r0 = ty * 32;
    int x = threadIdx.x, y = threadIdx.y;
#pragma unroll
    for (int i = 0; i < 32; i += 8)
        t[y + i][x] = in[(size_t)(r0 + y + i) * ldin + c0 + x];
    __syncthreads();
#pragma unroll
    for (int i = 0; i < 32; i += 8)
        out[(size_t)(c0 + y + i) * ldout + r0 + x] = __float2half_rn(t[x][y + i]);
}

// ---------------------------------------------------------------------------
// Fused flash-attention (fp16 mma.sync), non-causal, additive key mask.
//   Per CTA: 64 query rows of one (batch, head). 128 threads, 4 warps.
// ---------------------------------------------------------------------------
__global__ void __launch_bounds__(128, 2)
flash_kernel(const __half* __restrict__ Qp, const __half* __restrict__ Kp,
             const __half* __restrict__ Vp, const int* __restrict__ mask,
             __half* __restrict__ Op, int ldq, int ldkv, int ldo,
             long long sQb, long long sKb, long long sOb) {
    constexpr int STH = 72;          // halves per smem row (64 + 8 pad)
    constexpr int ST32 = STH / 2;    // 36 u32 per row
    constexpr int RB  = STH * 2;     // 144 bytes
    constexpr int TSZ = 64 * RB;     // 9216 bytes per tile
    const int KS = TSZ;
    const int VS = TSZ * 3;
    const int MK = TSZ * 5;

    extern __shared__ char smem[];
    uint32_t sb = smem_u32(smem);

    int tid = threadIdx.x, w = tid >> 5, lane = tid & 31;
    int lr = lane >> 2, lc = lane & 3;
    int qt = blockIdx.x, h = blockIdx.y, bz = blockIdx.z;

    const __half* Q = Qp + bz * sQb + (size_t)h * HD + (size_t)qt * 64 * ldq;
    const __half* K = Kp + bz * sKb + (size_t)h * HD;
    const __half* V = Vp + bz * sKb + (size_t)h * HD;
    const int* mrow = mask + bz * NSEQ;
    __half* O = Op + bz * sOb + (size_t)h * HD + (size_t)qt * 64 * ldo;

    auto load_kv = [&](int buf, int c) {
#pragma unroll
        for (int i = 0; i < 4; i++) {
            int idx = tid + i * 128, row = idx >> 3, col = idx & 7;
            CP_ASYNC16(sb + KS + buf * TSZ + row * RB + col * 16,
                       K + (size_t)(c * 64 + row) * ldkv + col * 8);
        }
#pragma unroll
        for (int i = 0; i < 4; i++) {
            int idx = tid + i * 128, row = idx >> 3, col = idx & 7;
            CP_ASYNC16(sb + VS + buf * TSZ + row * RB + col * 16,
                       V + (size_t)(c * 64 + row) * ldkv + col * 8);
        }
        if (tid < 16)
            CP_ASYNC16(sb + MK + buf * 256 + tid * 16, mrow + c * 64 + tid * 4);
        CP_COMMIT();
    };

#pragma unroll
    for (int i = 0; i < 4; i++) {
        int idx = tid + i * 128, row = idx >> 3, col = idx & 7;
        CP_ASYNC16(sb + row * RB + col * 16, Q + (size_t)row * ldq + col * 8);
    }
    CP_COMMIT();
    load_kv(0, 0);
    asm volatile("cp.async.wait_group 0;" ::: "memory");
    __syncthreads();

    const uint32_t* Qs = (const uint32_t*)smem;
    uint32_t qf[4][4];
    {
        int m0 = w * 16 + lr;
#pragma unroll
        for (int ds = 0; ds < 4; ds++) {
            qf[ds][0] = Qs[m0 * ST32 + ds * 8 + lc];
            qf[ds][1] = Qs[(m0 + 8) * ST32 + ds * 8 + lc];
            qf[ds][2] = Qs[m0 * ST32 + ds * 8 + 4 + lc];
            qf[ds][3] = Qs[(m0 + 8) * ST32 + ds * 8 + 4 + lc];
        }
    }

    float o[8][4];
#pragma unroll
    for (int dt = 0; dt < 8; dt++)
        o[dt][0] = o[dt][1] = o[dt][2] = o[dt][3] = 0.f;
    float m0r = -1e30f, m1r = -1e30f, l0 = 0.f, l1 = 0.f;

    for (int c = 0; c < 16; c++) {
        int buf = c & 1;
        asm volatile("cp.async.wait_group 0;" ::: "memory");
        __syncthreads();
        if (c + 1 < 16) load_kv(buf ^ 1, c + 1);

        const uint32_t* Ks = (const uint32_t*)(smem + KS + buf * TSZ);
        uint32_t vbase = sb + VS + buf * TSZ;
        const int* mk = (const int*)(smem + MK + buf * 256);

        float s[8][4];
#pragma unroll
        for (int j = 0; j < 8; j++) {
            s[j][0] = s[j][1] = s[j][2] = s[j][3] = 0.f;
#pragma unroll
            for (int ds = 0; ds < 4; ds++) {
                uint32_t bk[2];
                bk[0] = Ks[(j * 8 + lr) * ST32 + ds * 8 + lc];
                bk[1] = Ks[(j * 8 + lr) * ST32 + ds * 8 + 4 + lc];
                mma16(s[j], qf[ds], bk);
            }
        }

        float mx0 = -1e30f, mx1 = -1e30f;
#pragma unroll
        for (int j = 0; j < 8; j++) {
            float ma0 = (mk[j * 8 + 2 * lc]     == 1) ? 0.f : -10000.f;
            float ma1 = (mk[j * 8 + 2 * lc + 1] == 1) ? 0.f : -10000.f;
            s[j][0] = s[j][0] * 0.125f + ma0;
            s[j][1] = s[j][1] * 0.125f + ma1;
            s[j][2] = s[j][2] * 0.125f + ma0;
            s[j][3] = s[j][3] * 0.125f + ma1;
            mx0 = fmaxf(mx0, fmaxf(s[j][0], s[j][1]));
            mx1 = fmaxf(mx1, fmaxf(s[j][2], s[j][3]));
        }
        mx0 = fmaxf(mx0, __shfl_xor_sync(0xffffffffu, mx0, 1));
        mx0 = fmaxf(mx0, __shfl_xor_sync(0xffffffffu, mx0, 2));
        mx1 = fmaxf(mx1, __shfl_xor_sync(0xffffffffu, mx1, 1));
        mx1 = fmaxf(mx1, __shfl_xor_sync(0xffffffffu, mx1, 2));

        float mn0 = fmaxf(m0r, mx0), mn1 = fmaxf(m1r, mx1);
        float al0 = __expf(m0r - mn0), al1 = __expf(m1r - mn1);
        m0r = mn0; m1r = mn1;

        float r0 = 0.f, r1 = 0.f;
#pragma unroll
        for (int j = 0; j < 8; j++) {
            s[j][0] = __expf(s[j][0] - m0r);
            s[j][1] = __expf(s[j][1] - m0r);
            s[j][2] = __expf(s[j][2] - m1r);
            s[j][3] = __expf(s[j][3] - m1r);
            r0 += s[j][0] + s[j][1];
            r1 += s[j][2] + s[j][3];
        }
        l0 = l0 * al0 + r0;
        l1 = l1 * al1 + r1;

#pragma unroll
        for (int dt = 0; dt < 8; dt++) {
            o[dt][0] *= al0; o[dt][1] *= al0;
            o[dt][2] *= al1; o[dt][3] *= al1;
        }

        int m = lane >> 3, rIn = lane & 7;
#pragma unroll
        for (int kb = 0; kb < 4; kb++) {
            uint32_t aP[4];
            aP[0] = pkh(s[2*kb][0],   s[2*kb][1]);
            aP[1] = pkh(s[2*kb][2],   s[2*kb][3]);
            aP[2] = pkh(s[2*kb+1][0], s[2*kb+1][1]);
            aP[3] = pkh(s[2*kb+1][2], s[2*kb+1][3]);
            int key = kb * 16 + ((m & 1) ? 8 : 0) + rIn;
#pragma unroll
            for (int dtp = 0; dtp < 4; dtp++) {
                int dcol = (2 * dtp + (m >> 1)) * 8;
                uint32_t addr = vbase + (uint32_t)(key * RB + dcol * 2);
                uint32_t bv[4];
                asm volatile("ldmatrix.sync.aligned.m8n8.x4.trans.shared.b16 "
                             "{%0,%1,%2,%3}, [%4];"
                             : "=r"(bv[0]), "=r"(bv[1]), "=r"(bv[2]), "=r"(bv[3])
                             : "r"(addr));
                mma16(o[2*dtp],     aP, bv);
                mma16(o[2*dtp + 1], aP, bv + 2);
            }
        }
    }

    l0 += __shfl_xor_sync(0xffffffffu, l0, 1);
    l0 += __shfl_xor_sync(0xffffffffu, l0, 2);
    l1 += __shfl_xor_sync(0xffffffffu, l1, 1);
    l1 += __shfl_xor_sync(0xffffffffu, l1, 2);
    float inv0 = 1.f / l0, inv1 = 1.f / l1;
    int row0 = w * 16 + lr, row1 = row0 + 8;
#pragma unroll
    for (int dt = 0; dt < 8; dt++) {
        int col = dt * 8 + 2 * lc;
        *(uint32_t*)(O + (size_t)row0 * ldo + col) = pkh(o[dt][0] * inv0, o[dt][1] * inv0);
        *(uint32_t*)(O + (size_t)row1 * ldo + col) = pkh(o[dt][2] * inv1, o[dt][3] * inv1);
    }
}

// ---------------------------------------------------------------------------
// fp16 mma.sync GEMM. C = A @ B^T (+bias f32)(+GELU)(res f32 / out f16 or f32)
// BM=BN=128, BK=32, 256 threads, 8 warps (2x4), warp tile 64x32.
// Operands via ldmatrix.x4. 3-stage cp.async, 2 CTA/SM (16 warps).
// mode: bit0 = GELU, bit1 = output f16 (else f32 with optional res add).
// ---------------------------------------------------------------------------
__global__ void __launch_bounds__(256, 2)
mm_h(const __half* __restrict__ A, const __half* __restrict__ B,
     const float* __restrict__ bias, const float* __restrict__ res,
     void* __restrict__ Cout, int K, int lda, int ldb, int ldc, int mode) {
    constexpr int BM = 128, BN = 128, BK = 32;
    constexpr int STH = BK + 8;            // 40 halves per row
    constexpr int RB = STH * 2;            // 80 bytes
    constexpr int OPB = BM * RB;           // 10240 bytes per operand stage
    constexpr int STG = 2 * OPB;           // 20480 per stage (A+B)
    constexpr int MT = 4, NT = 4;          // 64x32 warp tile

    extern __shared__ char smem[];
    uint32_t sb = smem_u32(smem);

    int tid = threadIdx.x;
    int wid = tid >> 5, lane = tid & 31;
    int warpM = wid >> 2, warpN = wid & 3;
    int lr = lane >> 2, lc = lane & 3;

    int rowBase = blockIdx.y * BM;
    int colBase = blockIdx.x * BN;

    float acc[MT][NT][4];
#pragma unroll
    for (int i = 0; i < MT; i++)
#pragma unroll
        for (int j = 0; j < NT; j++)
#pragma unroll
            for (int q = 0; q < 4; q++) acc[i][j][q] = 0.f;

    auto load_stage = [&](int buf, int k0) {
#pragma unroll
        for (int i = 0; i < 2; i++) {                   // A: 128 rows x 4 x16B
            int idx = tid + i * 256;
            int row = idx >> 2, c = idx & 3;
            CP_ASYNC16(sb + buf * STG + (uint32_t)(row * RB + c * 16),
                       A + (size_t)(rowBase + row) * lda + k0 + c * 8);
        }
#pragma unroll
        for (int i = 0; i < 2; i++) {                   // B
            int idx = tid + i * 256;
            int row = idx >> 2, c = idx & 3;
            CP_ASYNC16(sb + buf * STG + OPB + (uint32_t)(row * RB + c * 16),
                       B + (size_t)(colBase + row) * ldb + k0 + c * 8);
        }
        CP_COMMIT();
    };

    int nsteps = K / BK;
    load_stage(0, 0);
    load_stage(1, BK);

    // ldmatrix lane addressing
    int l16 = lane & 15;
    int ahi = (lane >> 4) << 3;            // +8 k-halves for lanes 16-31
    int bgrp = lane >> 3;                  // 0..3
    int brow = ((bgrp & 2) << 2) + (lane & 7);   // +8 rows for groups 2,3
    int bcol = (bgrp & 1) << 3;            // +8 k-halves for odd groups

    for (int s = 0; s < nsteps; s++) {
        int buf = s % 3;
        if (s + 1 < nsteps) asm volatile("cp.async.wait_group 1;" ::: "memory");
        else                asm volatile("cp.async.wait_group 0;" ::: "memory");
        __syncthreads();
        if (s + 2 < nsteps) load_stage((s + 2) % 3, (s + 2) * BK);

        uint32_t abase = sb + buf * STG;
        uint32_t bbase = abase + OPB;
#pragma unroll
        for (int kk2 = 0; kk2 < 2; kk2++) {             // two k16 steps
            int kc = kk2 * 16;
            uint32_t af[MT][4], bf[NT][2];
#pragma unroll
            for (int i = 0; i < MT; i++) {
                int m0 = warpM * 64 + i * 16;
                uint32_t addr = abase + (uint32_t)((m0 + l16) * RB + (kc + ahi) * 2);
                LDM_X4(af[i][0], af[i][1], af[i][2], af[i][3], addr);
            }
#pragma unroll
            for (int jj = 0; jj < 2; jj++) {
                int n0 = warpN * 32 + jj * 16;
                uint32_t addr = bbase + (uint32_t)((n0 + brow) * RB + (kc + bcol) * 2);
                LDM_X4(bf[2*jj][0], bf[2*jj][1], bf[2*jj+1][0], bf[2*jj+1][1], addr);
            }
#pragma unroll
            for (int i = 0; i < MT; i++)
#pragma unroll
                for (int j = 0; j < NT; j++)
                    mma16(acc[i][j], af[i], bf[j]);
        }
    }
    __syncthreads();

    bool gelu = mode & 1, outh = mode & 2;
#pragma unroll
    for (int i = 0; i < MT; i++) {
#pragma unroll
        for (int j = 0; j < NT; j++) {
#pragma unroll
            for (int h = 0; h < 2; h++) {
                int r = rowBase + warpM * 64 + i * 16 + lr + h * 8;
                int cb = colBase + warpN * 32 + j * 8 + lc * 2;
                float v0 = acc[i][j][h * 2 + 0];
                float v1 = acc[i][j][h * 2 + 1];
                if (bias) { v0 += bias[cb]; v1 += bias[cb + 1]; }
                if (gelu) {
                    v0 = 0.5f * v0 * (1.f + erff(v0 * 0.70710678118654752f));
                    v1 = 0.5f * v1 * (1.f + erff(v1 * 0.70710678118654752f));
                }
                size_t off = (size_t)r * ldc + cb;
                if (outh) {
                    *(uint32_t*)((__half*)Cout + off) = pkh(v0, v1);
                } else {
                    if (res) {
                        float2 rv = *(const float2*)(res + off);
                        v0 += rv.x; v1 += rv.y;
                    }
                    *(float2*)((float*)Cout + off) = make_float2(v0, v1);
                }
            }
        }
    }
}

// ---------------------------------------------------------------------------
// Host-side launch orchestration
// ---------------------------------------------------------------------------
extern "C" void kernel_launch(void* const* d_in, const int* in_sizes, int n_in,
                              void* d_out, int out_size) {
    const float* x_in     = (const float*)d_in[0];
    const float* c_in     = (const float*)d_in[1];
    const int*   mask     = (const int*)d_in[2];
    const float* sa_qkv_w = (const float*)d_in[3];
    const float* sa_qkv_b = (const float*)d_in[4];
    const float* sa_proj_w= (const float*)d_in[5];
    const float* sa_proj_b= (const float*)d_in[6];
    const float* ca_q_w   = (const float*)d_in[7];
    const float* ca_q_b   = (const float*)d_in[8];
    const float* ca_k_w   = (const float*)d_in[9];
    const float* ca_k_b   = (const float*)d_in[10];
    const float* ca_v_w   = (const float*)d_in[11];
    const float* ca_v_b   = (const float*)d_in[12];
    const float* ca_proj_w= (const float*)d_in[13];
    const float* ca_proj_b= (const float*)d_in[14];
    const float* fc1_w    = (const float*)d_in[15];
    const float* fc1_b    = (const float*)d_in[16];
    const float* fc2_w    = (const float*)d_in[17];
    const float* fc2_b    = (const float*)d_in[18];

    float* xb = (float*)d_out;

    __half *gh, *gqkv, *gattn, *gmlp, *gwt;
    float *gbias;
    cudaGetSymbolAddress((void**)&gh,    g_h);
    cudaGetSymbolAddress((void**)&gqkv,  g_qkv);
    cudaGetSymbolAddress((void**)&gattn, g_attn);
    cudaGetSymbolAddress((void**)&gmlp,  g_mlp);
    cudaGetSymbolAddress((void**)&gwt,   g_wt);
    cudaGetSymbolAddress((void**)&gbias, g_bias);

    const int SMEM_MM = 3 * 2 * 128 * 80;                 // 61440
    const int SMEM_FLASH = 5 * (64 * 144) + 2 * 256;      // 46592
    cudaFuncSetAttribute(mm_h, cudaFuncAttributeMaxDynamicSharedMemorySize, SMEM_MM);
    cudaFuncSetAttribute(flash_kernel, cudaFuncAttributeMaxDynamicSharedMemorySize, SMEM_FLASH);

    dim3 tblock(32, 8);
    dim3 fgrid(NSEQ / 64, HEADS, NBAT);

    // ---- batched weight transposes (one launch) ----
    TArgs ta;
    const float* wins[8] = { sa_qkv_w, sa_proj_w, ca_q_w, ca_k_w,
                             ca_v_w, ca_proj_w, fc1_w, fc2_w };
    __half* wouts[8] = { gwt + W_QKV, gwt + W_SAPROJ, gwt + W_CAQ, gwt + W_CAK,
                         gwt + W_CAV, gwt + W_CAPROJ, gwt + W_FC1, gwt + W_FC2 };
    int rows[8] = { 1024, 1024, 1024, 1024, 1024, 1024, 1024, 4096 };
    int cols[8] = { 3072, 1024, 1024, 1024, 1024, 1024, 4096, 1024 };
    int acc_t = 0;
    for (int i = 0; i < 8; i++) {
        ta.in[i] = wins[i]; ta.out[i] = wouts[i];
        ta.ldin[i] = cols[i]; ta.ldout[i] = rows[i];
        ta.tilesX[i] = cols[i] / 32;
        acc_t += (rows[i] / 32) * (cols[i] / 32);
        ta.tileEnd[i] = acc_t;
    }

    cudaMemcpyAsync(xb, x_in, (size_t)TOK * CDIM * sizeof(float),
                    cudaMemcpyDeviceToDevice, 0);
    cudaMemcpyAsync(gbias, ca_k_b, CDIM * sizeof(float), cudaMemcpyDeviceToDevice, 0);
    cudaMemcpyAsync(gbias + CDIM, ca_v_b, CDIM * sizeof(float), cudaMemcpyDeviceToDevice, 0);
    multi_transpose<<<acc_t, tblock>>>(ta);
    half_copy<<<TOK * CDIM / 4 / 256, 256>>>(c_in, gmlp);   // f16 copy of c

    // ===================== self-attention =====================
    ln_kernel<<<TOK, 256>>>(xb, gh);

    mm_h<<<dim3(3072/128, TOK/128), 256, SMEM_MM>>>(
        gh, gwt + W_QKV, sa_qkv_b, nullptr, gqkv, 1024, 1024, 1024, 3072, 2);

    flash_kernel<<<fgrid, 128, SMEM_FLASH>>>(
        gqkv, gqkv + CDIM, gqkv + 2 * CDIM, mask, gattn, 3072, 3072, 1024,
        (long long)NSEQ * 3 * CDIM, (long long)NSEQ * 3 * CDIM,
        (long long)NSEQ * CDIM);

    mm_h<<<dim3(CDIM/128, TOK/128), 256, SMEM_MM>>>(
        gattn, gwt + W_SAPROJ, sa_proj_b, xb, xb, 1024, 1024, 1024, 1024, 0);

    // ===================== cross-attention =====================
    ln_kernel<<<TOK, 256>>>(xb, gh);

    __half* gq  = gqkv;
    __half* gkv = gqkv + (size_t)TOK * CDIM;   // interleaved [TOK][2048]: k | v
    __half* gcr = gmlp;

    mm_h<<<dim3(CDIM/128, TOK/128), 256, SMEM_MM>>>(
        gh, gwt + W_CAQ, ca_q_b, nullptr, gq, 1024, 1024, 1024, 1024, 2);
    // fused K|V projection: B = [ca_k_w^T ; ca_v_w^T] contiguous, N=2048
    mm_h<<<dim3(2048/128, TOK/128), 256, SMEM_MM>>>(
        gcr, gwt + W_CAK, gbias, nullptr, gkv, 1024, 1024, 1024, 2048, 2);

    flash_kernel<<<fgrid, 128, SMEM_FLASH>>>(
        gq, gkv, gkv + CDIM, mask, gattn, 1024, 2048, 1024,
        (long long)NSEQ * CDIM, (long long)NSEQ * 2048,
        (long long)NSEQ * CDIM);

    mm_h<<<dim3(CDIM/128, TOK/128), 256, SMEM_MM>>>(
        gattn, gwt + W_CAPROJ, ca_proj_b, xb, xb, 1024, 1024, 1024, 1024, 0);

    // ===================== MLP =====================
    ln_kernel<<<TOK, 256>>>(xb, gh);

    mm_h<<<dim3(4096/128, TOK/128), 256, SMEM_MM>>>(
        gh, gwt + W_FC1, fc1_b, nullptr, gmlp, 1024, 1024, 1024, 4096, 3);

    mm_h<<<dim3(CDIM/128, TOK/128), 256, SMEM_MM>>>(
        gmlp, gwt + W_FC2, fc2_b, xb, xb, 4096, 4096, 4096, 1024, 0);
}

// round 13
// speedup vs baseline: 2.6706x; 1.0247x over previous
#include <cuda_runtime.h>
#include <cuda_fp16.h>
#include <math.h>
#include <stdint.h>

// Problem constants
#define TOK   4096         // B*N
#define CDIM  1024
#define HEADS 16
#define NBAT  4
#define NSEQ  1024
#define HD    64

// Scratch (device globals: allocation-free per harness rules)
__device__ __align__(256) __half g_h[TOK * CDIM];                 // 8 MB  LN out
__device__ __align__(256) __half g_qkv[TOK * 3 * CDIM];           // 24 MB q / interleaved kv
__device__ __align__(256) __half g_attn[TOK * CDIM];              // 8 MB
__device__ __align__(256) __half g_mlp[TOK * 4 * CDIM];           // 32 MB (also f16 c)
__device__ __align__(256) __half g_wt[16777216];                  // 32 MB transposed weights
__device__ __align__(256) float  g_bias[2048];                    // ca_k_b || ca_v_b

// g_wt half-element offsets
#define W_QKV    0
#define W_SAPROJ 3145728
#define W_CAQ    4194304
#define W_CAK    5242880
#define W_CAV    6291456
#define W_CAPROJ 7340032
#define W_FC1    8388608
#define W_FC2    12582912

// ---------------------------------------------------------------------------
// Helpers
// ---------------------------------------------------------------------------
__device__ __forceinline__ uint32_t smem_u32(const void* p) {
    uint32_t a;
    asm("{ .reg .u64 t; cvta.to.shared.u64 t, %1; cvt.u32.u64 %0, t; }" : "=r"(a) : "l"(p));
    return a;
}
// pack(lo, hi) -> f16x2
__device__ __forceinline__ uint32_t pkh(float lo, float hi) {
    uint32_t r;
    asm("cvt.rn.f16x2.f32 %0, %1, %2;" : "=r"(r) : "f"(hi), "f"(lo));
    return r;
}
#define CP_ASYNC16(dst, src) \
    asm volatile("cp.async.cg.shared.global [%0], [%1], 16;" :: "r"(dst), "l"(src) : "memory")
#define CP_COMMIT()  asm volatile("cp.async.commit_group;" ::: "memory")

__device__ __forceinline__ void mma16(float* d, const uint32_t* a, const uint32_t* b) {
    asm volatile("mma.sync.aligned.m16n8k16.row.col.f32.f16.f16.f32 "
                 "{%0,%1,%2,%3}, {%4,%5,%6,%7}, {%8,%9}, {%0,%1,%2,%3};"
                 : "+f"(d[0]), "+f"(d[1]), "+f"(d[2]), "+f"(d[3])
                 : "r"(a[0]), "r"(a[1]), "r"(a[2]), "r"(a[3]), "r"(b[0]), "r"(b[1]));
}
#define LDM_X4(r0, r1, r2, r3, addr) \
    asm volatile("ldmatrix.sync.aligned.m8n8.x4.shared.b16 {%0,%1,%2,%3}, [%4];" \
                 : "=r"(r0), "=r"(r1), "=r"(r2), "=r"(r3) : "r"(addr))

// ---------------------------------------------------------------------------
// LayerNorm (no affine, eps=1e-6): f32 in, f16 out (feeds MMA only)
// ---------------------------------------------------------------------------
__global__ void ln_kernel(const float* __restrict__ in, __half* __restrict__ out) {
    __shared__ float sred[256];
    int row = blockIdx.x;
    const float4* p = (const float4*)(in + (size_t)row * CDIM);
    float4 v = p[threadIdx.x];
    float s = v.x + v.y + v.z + v.w;
    sred[threadIdx.x] = s; __syncthreads();
    for (int o = 128; o > 0; o >>= 1) {
        if (threadIdx.x < o) sred[threadIdx.x] += sred[threadIdx.x + o];
        __syncthreads();
    }
    float mean = sred[0] * (1.f / CDIM);
    __syncthreads();
    float dx = v.x-mean, dy = v.y-mean, dz = v.z-mean, dw = v.w-mean;
    sred[threadIdx.x] = dx*dx + dy*dy + dz*dz + dw*dw; __syncthreads();
    for (int o = 128; o > 0; o >>= 1) {
        if (threadIdx.x < o) sred[threadIdx.x] += sred[threadIdx.x + o];
        __syncthreads();
    }
    float inv = rsqrtf(sred[0] * (1.f / CDIM) + 1e-6f);
    uint2 r;
    r.x = pkh(dx * inv, dy * inv);
    r.y = pkh(dz * inv, dw * inv);
    ((uint2*)(out + (size_t)row * CDIM))[threadIdx.x] = r;
}

// ---------------------------------------------------------------------------
// f32 -> f16 copy (for raw c input feeding K/V GEMMs)
// ---------------------------------------------------------------------------
__global__ void half_copy(const float* __restrict__ in, __half* __restrict__ out) {
    size_t i = (size_t)blockIdx.x * 256 + threadIdx.x;
    float4 v = ((const float4*)in)[i];
    uint2 r;
    r.x = pkh(v.x, v.y);
    r.y = pkh(v.z, v.w);
    ((uint2*)out)[i] = r;
}

// ---------------------------------------------------------------------------
// Batched multi-weight 32x32 tiled transpose -> f16 (one launch)
// ---------------------------------------------------------------------------
struct TArgs {
    const float* in[8];
    __half* out[8];
    int ldin[8];
    int ldout[8];
    int tilesX[8];
    int tileEnd[8];
};

__global__ void multi_transpose(TArgs a) {
    __shared__ float t[32][33];
    int bid = blockIdx.x;
    int s = 0;
#pragma unroll
    for (int i = 0; i < 8; i++)
        if (bid >= a.tileEnd[i]) s = i + 1;
    int t0 = s ? a.tileEnd[s - 1] : 0;
    int lt = bid - t0;
    int tx = lt % a.tilesX[s], ty = lt / a.tilesX[s];
    const float* in = a.in[s];
    __half* out = a.out[s];
    int ldin = a.ldin[s], ldout = a.ldout[s];
    int c0 = tx * 32, r0 = ty * 32;
    int x = threadIdx.x, y = threadIdx.y;
#pragma unroll
    for (int i = 0; i < 32; i += 8)
        t[y + i][x] = in[(size_t)(r0 + y + i) * ldin + c0 + x];
    __syncthreads();
#pragma unroll
    for (int i = 0; i < 32; i += 8)
        out[(size_t)(c0 + y + i) * ldout + r0 + x] = __float2half_rn(t[x][y + i]);
}

// ---------------------------------------------------------------------------
// Fused flash-attention (fp16 mma.sync), non-causal, additive key mask.
//   Per CTA: 64 query rows of one (batch, head). 128 threads, 4 warps.
// ---------------------------------------------------------------------------
__global__ void __launch_bounds__(128, 2)
flash_kernel(const __half* __restrict__ Qp, const __half* __restrict__ Kp,
             const __half* __restrict__ Vp, const int* __restrict__ mask,
             __half* __restrict__ Op, int ldq, int ldkv, int ldo,
             long long sQb, long long sKb, long long sOb) {
    constexpr int STH = 72;          // halves per smem row (64 + 8 pad)
    constexpr int ST32 = STH / 2;    // 36 u32 per row
    constexpr int RB  = STH * 2;     // 144 bytes
    constexpr int TSZ = 64 * RB;     // 9216 bytes per tile
    const int KS = TSZ;
    const int VS = TSZ * 3;
    const int MK = TSZ * 5;

    extern __shared__ char smem[];
    uint32_t sb = smem_u32(smem);

    int tid = threadIdx.x, w = tid >> 5, lane = tid & 31;
    int lr = lane >> 2, lc = lane & 3;
    int qt = blockIdx.x, h = blockIdx.y, bz = blockIdx.z;

    const __half* Q = Qp + bz * sQb + (size_t)h * HD + (size_t)qt * 64 * ldq;
    const __half* K = Kp + bz * sKb + (size_t)h * HD;
    const __half* V = Vp + bz * sKb + (size_t)h * HD;
    const int* mrow = mask + bz * NSEQ;
    __half* O = Op + bz * sOb + (size_t)h * HD + (size_t)qt * 64 * ldo;

    auto load_kv = [&](int buf, int c) {
#pragma unroll
        for (int i = 0; i < 4; i++) {
            int idx = tid + i * 128, row = idx >> 3, col = idx & 7;
            CP_ASYNC16(sb + KS + buf * TSZ + row * RB + col * 16,
                       K + (size_t)(c * 64 + row) * ldkv + col * 8);
        }
#pragma unroll
        for (int i = 0; i < 4; i++) {
            int idx = tid + i * 128, row = idx >> 3, col = idx & 7;
            CP_ASYNC16(sb + VS + buf * TSZ + row * RB + col * 16,
                       V + (size_t)(c * 64 + row) * ldkv + col * 8);
        }
        if (tid < 16)
            CP_ASYNC16(sb + MK + buf * 256 + tid * 16, mrow + c * 64 + tid * 4);
        CP_COMMIT();
    };

#pragma unroll
    for (int i = 0; i < 4; i++) {
        int idx = tid + i * 128, row = idx >> 3, col = idx & 7;
        CP_ASYNC16(sb + row * RB + col * 16, Q + (size_t)row * ldq + col * 8);
    }
    CP_COMMIT();
    load_kv(0, 0);
    asm volatile("cp.async.wait_group 0;" ::: "memory");
    __syncthreads();

    const uint32_t* Qs = (const uint32_t*)smem;
    uint32_t qf[4][4];
    {
        int m0 = w * 16 + lr;
#pragma unroll
        for (int ds = 0; ds < 4; ds++) {
            qf[ds][0] = Qs[m0 * ST32 + ds * 8 + lc];
            qf[ds][1] = Qs[(m0 + 8) * ST32 + ds * 8 + lc];
            qf[ds][2] = Qs[m0 * ST32 + ds * 8 + 4 + lc];
            qf[ds][3] = Qs[(m0 + 8) * ST32 + ds * 8 + 4 + lc];
        }
    }

    float o[8][4];
#pragma unroll
    for (int dt = 0; dt < 8; dt++)
        o[dt][0] = o[dt][1] = o[dt][2] = o[dt][3] = 0.f;
    float m0r = -1e30f, m1r = -1e30f, l0 = 0.f, l1 = 0.f;

    for (int c = 0; c < 16; c++) {
        int buf = c & 1;
        asm volatile("cp.async.wait_group 0;" ::: "memory");
        __syncthreads();
        if (c + 1 < 16) load_kv(buf ^ 1, c + 1);

        const uint32_t* Ks = (const uint32_t*)(smem + KS + buf * TSZ);
        uint32_t vbase = sb + VS + buf * TSZ;
        const int* mk = (const int*)(smem + MK + buf * 256);

        float s[8][4];
#pragma unroll
        for (int j = 0; j < 8; j++) {
            s[j][0] = s[j][1] = s[j][2] = s[j][3] = 0.f;
#pragma unroll
            for (int ds = 0; ds < 4; ds++) {
                uint32_t bk[2];
                bk[0] = Ks[(j * 8 + lr) * ST32 + ds * 8 + lc];
                bk[1] = Ks[(j * 8 + lr) * ST32 + ds * 8 + 4 + lc];
                mma16(s[j], qf[ds], bk);
            }
        }

        float mx0 = -1e30f, mx1 = -1e30f;
#pragma unroll
        for (int j = 0; j < 8; j++) {
            float ma0 = (mk[j * 8 + 2 * lc]     == 1) ? 0.f : -10000.f;
            float ma1 = (mk[j * 8 + 2 * lc + 1] == 1) ? 0.f : -10000.f;
            s[j][0] = s[j][0] * 0.125f + ma0;
            s[j][1] = s[j][1] * 0.125f + ma1;
            s[j][2] = s[j][2] * 0.125f + ma0;
            s[j][3] = s[j][3] * 0.125f + ma1;
            mx0 = fmaxf(mx0, fmaxf(s[j][0], s[j][1]));
            mx1 = fmaxf(mx1, fmaxf(s[j][2], s[j][3]));
        }
        mx0 = fmaxf(mx0, __shfl_xor_sync(0xffffffffu, mx0, 1));
        mx0 = fmaxf(mx0, __shfl_xor_sync(0xffffffffu, mx0, 2));
        mx1 = fmaxf(mx1, __shfl_xor_sync(0xffffffffu, mx1, 1));
        mx1 = fmaxf(mx1, __shfl_xor_sync(0xffffffffu, mx1, 2));

        float mn0 = fmaxf(m0r, mx0), mn1 = fmaxf(m1r, mx1);
        float al0 = __expf(m0r - mn0), al1 = __expf(m1r - mn1);
        m0r = mn0; m1r = mn1;

        float r0 = 0.f, r1 = 0.f;
#pragma unroll
        for (int j = 0; j < 8; j++) {
            s[j][0] = __expf(s[j][0] - m0r);
            s[j][1] = __expf(s[j][1] - m0r);
            s[j][2] = __expf(s[j][2] - m1r);
            s[j][3] = __expf(s[j][3] - m1r);
            r0 += s[j][0] + s[j][1];
            r1 += s[j][2] + s[j][3];
        }
        l0 = l0 * al0 + r0;
        l1 = l1 * al1 + r1;

#pragma unroll
        for (int dt = 0; dt < 8; dt++) {
            o[dt][0] *= al0; o[dt][1] *= al0;
            o[dt][2] *= al1; o[dt][3] *= al1;
        }

        int m = lane >> 3, rIn = lane & 7;
#pragma unroll
        for (int kb = 0; kb < 4; kb++) {
            uint32_t aP[4];
            aP[0] = pkh(s[2*kb][0],   s[2*kb][1]);
            aP[1] = pkh(s[2*kb][2],   s[2*kb][3]);
            aP[2] = pkh(s[2*kb+1][0], s[2*kb+1][1]);
            aP[3] = pkh(s[2*kb+1][2], s[2*kb+1][3]);
            int key = kb * 16 + ((m & 1) ? 8 : 0) + rIn;
#pragma unroll
            for (int dtp = 0; dtp < 4; dtp++) {
                int dcol = (2 * dtp + (m >> 1)) * 8;
                uint32_t addr = vbase + (uint32_t)(key * RB + dcol * 2);
                uint32_t bv[4];
                asm volatile("ldmatrix.sync.aligned.m8n8.x4.trans.shared.b16 "
                             "{%0,%1,%2,%3}, [%4];"
                             : "=r"(bv[0]), "=r"(bv[1]), "=r"(bv[2]), "=r"(bv[3])
                             : "r"(addr));
                mma16(o[2*dtp],     aP, bv);
                mma16(o[2*dtp + 1], aP, bv + 2);
            }
        }
    }

    l0 += __shfl_xor_sync(0xffffffffu, l0, 1);
    l0 += __shfl_xor_sync(0xffffffffu, l0, 2);
    l1 += __shfl_xor_sync(0xffffffffu, l1, 1);
    l1 += __shfl_xor_sync(0xffffffffu, l1, 2);
    float inv0 = 1.f / l0, inv1 = 1.f / l1;
    int row0 = w * 16 + lr, row1 = row0 + 8;
#pragma unroll
    for (int dt = 0; dt < 8; dt++) {
        int col = dt * 8 + 2 * lc;
        *(uint32_t*)(O + (size_t)row0 * ldo + col) = pkh(o[dt][0] * inv0, o[dt][1] * inv0);
        *(uint32_t*)(O + (size_t)row1 * ldo + col) = pkh(o[dt][2] * inv1, o[dt][3] * inv1);
    }
}

// ---------------------------------------------------------------------------
// fp16 mma.sync GEMM. C = A @ B^T (+bias f32)(+GELU)(res f32 / out f16 or f32)
// BM=BN=128, BK=64, 256 threads, 8 warps (2x4), warp tile 64x32.
// Operands via ldmatrix.x4. 2-stage cp.async (73.7KB), 2 CTA/SM (16 warps).
// mode: bit0 = GELU, bit1 = output f16 (else f32 with optional res add).
// ---------------------------------------------------------------------------
__global__ void __launch_bounds__(256, 2)
mm_h(const __half* __restrict__ A, const __half* __restrict__ B,
     const float* __restrict__ bias, const float* __restrict__ res,
     void* __restrict__ Cout, int K, int lda, int ldb, int ldc, int mode) {
    constexpr int BM = 128, BN = 128, BK = 64;
    constexpr int STH = BK + 8;            // 72 halves per row
    constexpr int RB = STH * 2;            // 144 bytes
    constexpr int OPB = BM * RB;           // 18432 bytes per operand stage
    constexpr int STG = 2 * OPB;           // 36864 per stage (A+B)
    constexpr int MT = 4, NT = 4;          // 64x32 warp tile

    extern __shared__ char smem[];
    uint32_t sb = smem_u32(smem);

    int tid = threadIdx.x;
    int wid = tid >> 5, lane = tid & 31;
    int warpM = wid >> 2, warpN = wid & 3;
    int lr = lane >> 2, lc = lane & 3;

    int rowBase = blockIdx.y * BM;
    int colBase = blockIdx.x * BN;

    float acc[MT][NT][4];
#pragma unroll
    for (int i = 0; i < MT; i++)
#pragma unroll
        for (int j = 0; j < NT; j++)
#pragma unroll
            for (int q = 0; q < 4; q++) acc[i][j][q] = 0.f;

    auto load_stage = [&](int buf, int k0) {
#pragma unroll
        for (int i = 0; i < 4; i++) {                   // A: 128 rows x 8 x16B
            int idx = tid + i * 256;
            int row = idx >> 3, c = idx & 7;
            CP_ASYNC16(sb + buf * STG + (uint32_t)(row * RB + c * 16),
                       A + (size_t)(rowBase + row) * lda + k0 + c * 8);
        }
#pragma unroll
        for (int i = 0; i < 4; i++) {                   // B
            int idx = tid + i * 256;
            int row = idx >> 3, c = idx & 7;
            CP_ASYNC16(sb + buf * STG + OPB + (uint32_t)(row * RB + c * 16),
                       B + (size_t)(colBase + row) * ldb + k0 + c * 8);
        }
        CP_COMMIT();
    };

    int nsteps = K / BK;
    load_stage(0, 0);
    load_stage(1, BK);

    // ldmatrix lane addressing
    int l16 = lane & 15;
    int ahi = (lane >> 4) << 3;            // +8 k-halves for lanes 16-31
    int bgrp = lane >> 3;                  // 0..3
    int brow = ((bgrp & 2) << 2) + (lane & 7);   // +8 rows for groups 2,3
    int bcol = (bgrp & 1) << 3;            // +8 k-halves for odd groups

    for (int s = 0; s < nsteps; s++) {
        int buf = s & 1;
        if (s + 1 < nsteps) asm volatile("cp.async.wait_group 1;" ::: "memory");
        else                asm volatile("cp.async.wait_group 0;" ::: "memory");
        __syncthreads();

        uint32_t abase = sb + buf * STG;
        uint32_t bbase = abase + OPB;
#pragma unroll
        for (int kk2 = 0; kk2 < 4; kk2++) {             // four k16 steps
            int kc = kk2 * 16;
            uint32_t af[MT][4], bf[NT][2];
#pragma unroll
            for (int i = 0; i < MT; i++) {
                int m0 = warpM * 64 + i * 16;
                uint32_t addr = abase + (uint32_t)((m0 + l16) * RB + (kc + ahi) * 2);
                LDM_X4(af[i][0], af[i][1], af[i][2], af[i][3], addr);
            }
#pragma unroll
            for (int jj = 0; jj < 2; jj++) {
                int n0 = warpN * 32 + jj * 16;
                uint32_t addr = bbase + (uint32_t)((n0 + brow) * RB + (kc + bcol) * 2);
                LDM_X4(bf[2*jj][0], bf[2*jj][1], bf[2*jj+1][0], bf[2*jj+1][1], addr);
            }
#pragma unroll
            for (int i = 0; i < MT; i++)
#pragma unroll
                for (int j = 0; j < NT; j++)
                    mma16(acc[i][j], af[i], bf[j]);
        }
        __syncthreads();
        if (s + 2 < nsteps) load_stage(buf, (s + 2) * BK);
    }

    bool gelu = mode & 1, outh = mode & 2;
#pragma unroll
    for (int i = 0; i < MT; i++) {
#pragma unroll
        for (int j = 0; j < NT; j++) {
#pragma unroll
            for (int h = 0; h < 2; h++) {
                int r = rowBase + warpM * 64 + i * 16 + lr + h * 8;
                int cb = colBase + warpN * 32 + j * 8 + lc * 2;
                float v0 = acc[i][j][h * 2 + 0];
                float v1 = acc[i][j][h * 2 + 1];
                if (bias) { v0 += bias[cb]; v1 += bias[cb + 1]; }
                if (gelu) {
                    v0 = 0.5f * v0 * (1.f + erff(v0 * 0.70710678118654752f));
                    v1 = 0.5f * v1 * (1.f + erff(v1 * 0.70710678118654752f));
                }
                size_t off = (size_t)r * ldc + cb;
                if (outh) {
                    *(uint32_t*)((__half*)Cout + off) = pkh(v0, v1);
                } else {
                    if (res) {
                        float2 rv = *(const float2*)(res + off);
                        v0 += rv.x; v1 += rv.y;
                    }
                    *(float2*)((float*)Cout + off) = make_float2(v0, v1);
                }
            }
        }
    }
}

// ---------------------------------------------------------------------------
// Host-side launch orchestration
// ---------------------------------------------------------------------------
extern "C" void kernel_launch(void* const* d_in, const int* in_sizes, int n_in,
                              void* d_out, int out_size) {
    const float* x_in     = (const float*)d_in[0];
    const float* c_in     = (const float*)d_in[1];
    const int*   mask     = (const int*)d_in[2];
    const float* sa_qkv_w = (const float*)d_in[3];
    const float* sa_qkv_b = (const float*)d_in[4];
    const float* sa_proj_w= (const float*)d_in[5];
    const float* sa_proj_b= (const float*)d_in[6];
    const float* ca_q_w   = (const float*)d_in[7];
    const float* ca_q_b   = (const float*)d_in[8];
    const float* ca_k_w   = (const float*)d_in[9];
    const float* ca_k_b   = (const float*)d_in[10];
    const float* ca_v_w   = (const float*)d_in[11];
    const float* ca_v_b   = (const float*)d_in[12];
    const float* ca_proj_w= (const float*)d_in[13];
    const float* ca_proj_b= (const float*)d_in[14];
    const float* fc1_w    = (const float*)d_in[15];
    const float* fc1_b    = (const float*)d_in[16];
    const float* fc2_w    = (const float*)d_in[17];
    const float* fc2_b    = (const float*)d_in[18];

    float* xb = (float*)d_out;

    __half *gh, *gqkv, *gattn, *gmlp, *gwt;
    float *gbias;
    cudaGetSymbolAddress((void**)&gh,    g_h);
    cudaGetSymbolAddress((void**)&gqkv,  g_qkv);
    cudaGetSymbolAddress((void**)&gattn, g_attn);
    cudaGetSymbolAddress((void**)&gmlp,  g_mlp);
    cudaGetSymbolAddress((void**)&gwt,   g_wt);
    cudaGetSymbolAddress((void**)&gbias, g_bias);

    const int SMEM_MM = 2 * 2 * 128 * 144;                // 73728
    const int SMEM_FLASH = 5 * (64 * 144) + 2 * 256;      // 46592
    cudaFuncSetAttribute(mm_h, cudaFuncAttributeMaxDynamicSharedMemorySize, SMEM_MM);
    cudaFuncSetAttribute(flash_kernel, cudaFuncAttributeMaxDynamicSharedMemorySize, SMEM_FLASH);

    dim3 tblock(32, 8);
    dim3 fgrid(NSEQ / 64, HEADS, NBAT);

    // ---- batched weight transposes (one launch) ----
    TArgs ta;
    const float* wins[8] = { sa_qkv_w, sa_proj_w, ca_q_w, ca_k_w,
                             ca_v_w, ca_proj_w, fc1_w, fc2_w };
    __half* wouts[8] = { gwt + W_QKV, gwt + W_SAPROJ, gwt + W_CAQ, gwt + W_CAK,
                         gwt + W_CAV, gwt + W_CAPROJ, gwt + W_FC1, gwt + W_FC2 };
    int rows[8] = { 1024, 1024, 1024, 1024, 1024, 1024, 1024, 4096 };
    int cols[8] = { 3072, 1024, 1024, 1024, 1024, 1024, 4096, 1024 };
    int acc_t = 0;
    for (int i = 0; i < 8; i++) {
        ta.in[i] = wins[i]; ta.out[i] = wouts[i];
        ta.ldin[i] = cols[i]; ta.ldout[i] = rows[i];
        ta.tilesX[i] = cols[i] / 32;
        acc_t += (rows[i] / 32) * (cols[i] / 32);
        ta.tileEnd[i] = acc_t;
    }

    cudaMemcpyAsync(xb, x_in, (size_t)TOK * CDIM * sizeof(float),
                    cudaMemcpyDeviceToDevice, 0);
    cudaMemcpyAsync(gbias, ca_k_b, CDIM * sizeof(float), cudaMemcpyDeviceToDevice, 0);
    cudaMemcpyAsync(gbias + CDIM, ca_v_b, CDIM * sizeof(float), cudaMemcpyDeviceToDevice, 0);
    multi_transpose<<<acc_t, tblock>>>(ta);
    half_copy<<<TOK * CDIM / 4 / 256, 256>>>(c_in, gmlp);   // f16 copy of c

    // ===================== self-attention =====================
    ln_kernel<<<TOK, 256>>>(xb, gh);

    mm_h<<<dim3(3072/128, TOK/128), 256, SMEM_MM>>>(
        gh, gwt + W_QKV, sa_qkv_b, nullptr, gqkv, 1024, 1024, 1024, 3072, 2);

    flash_kernel<<<fgrid, 128, SMEM_FLASH>>>(
        gqkv, gqkv + CDIM, gqkv + 2 * CDIM, mask, gattn, 3072, 3072, 1024,
        (long long)NSEQ * 3 * CDIM, (long long)NSEQ * 3 * CDIM,
        (long long)NSEQ * CDIM);

    mm_h<<<dim3(CDIM/128, TOK/128), 256, SMEM_MM>>>(
        gattn, gwt + W_SAPROJ, sa_proj_b, xb, xb, 1024, 1024, 1024, 1024, 0);

    // ===================== cross-attention =====================
    ln_kernel<<<TOK, 256>>>(xb, gh);

    __half* gq  = gqkv;
    __half* gkv = gqkv + (size_t)TOK * CDIM;   // interleaved [TOK][2048]: k | v
    __half* gcr = gmlp;

    mm_h<<<dim3(CDIM/128, TOK/128), 256, SMEM_MM>>>(
        gh, gwt + W_CAQ, ca_q_b, nullptr, gq, 1024, 1024, 1024, 1024, 2);
    // fused K|V projection: B = [ca_k_w^T ; ca_v_w^T] contiguous, N=2048
    mm_h<<<dim3(2048/128, TOK/128), 256, SMEM_MM>>>(
        gcr, gwt + W_CAK, gbias, nullptr, gkv, 1024, 1024, 1024, 2048, 2);

    flash_kernel<<<fgrid, 128, SMEM_FLASH>>>(
        gq, gkv, gkv + CDIM, mask, gattn, 1024, 2048, 1024,
        (long long)NSEQ * CDIM, (long long)NSEQ * 2048,
        (long long)NSEQ * CDIM);

    mm_h<<<dim3(CDIM/128, TOK/128), 256, SMEM_MM>>>(
        gattn, gwt + W_CAPROJ, ca_proj_b, xb, xb, 1024, 1024, 1024, 1024, 0);

    // ===================== MLP =====================
    ln_kernel<<<TOK, 256>>>(xb, gh);

    mm_h<<<dim3(4096/128, TOK/128), 256, SMEM_MM>>>(
        gh, gwt + W_FC1, fc1_b, nullptr, gmlp, 1024, 1024, 1024, 4096, 3);

    mm_h<<<dim3(CDIM/128, TOK/128), 256, SMEM_MM>>>(
        gmlp, gwt + W_FC2, fc2_b, xb, xb, 4096, 4096, 4096, 1024, 0);
}